// round 1
// baseline (speedup 1.0000x reference)
#include <cuda_runtime.h>
#include <math.h>
#include <float.h>

// Problem constants
#define DIM   512
#define KLAT  360      // latent nodes
#define KP    384      // padded K (multiple of 64)
#define MRBF  145      // 12*12 + 1 bias
#define BM    64       // rows of t per block
#define DK    16       // d-chunk
#define YSTRIDE (DK + 4)   // 20 -> conflict-free for float4 LDS

// Scratch (device globals; no allocation allowed)
__device__ float  g_phi[KLAT * MRBF];
__device__ float  g_Y[KP * DIM];        // Y[k][d], rows 360..383 zero
__device__ float  g_ynorm[KP];
__device__ double g_partial[4096];      // per-block log-sum partials

// ---------------------------------------------------------------------------
// phi[k][m] = exp(-3 * ||x_k - c_m||^2)  (sigma = 1/6, 2*sigma = 1/3)
// ---------------------------------------------------------------------------
__global__ void phi_kernel() {
    int idx = blockIdx.x * blockDim.x + threadIdx.x;
    if (idx >= KLAT * MRBF) return;
    int k = idx / MRBF, m = idx % MRBF;
    float val;
    if (m == MRBF - 1) {
        val = 1.0f;  // bias column
    } else {
        int ia = k / 18, ib = k % 18;
        double x0 = -1.0 + ia * (2.0 / 19.0);
        double x1 = -1.0 + ib * (2.0 / 17.0);
        int mi = m / 12, mj = m % 12;
        double step = (2.0 - 2.0 / 12.0) / 11.0;
        double c0 = -1.0 + 1.0 / 12.0 + mi * step;
        double c1 = -1.0 + 1.0 / 12.0 + mj * step;
        double d2 = (x0 - c0) * (x0 - c0) + (x1 - c1) * (x1 - c1);
        val = (float)exp(-3.0 * d2);   // d2 / (2*sigma), sigma = 1/6
    }
    g_phi[idx] = val;
}

// ---------------------------------------------------------------------------
// Y = phi @ W  (360x512), ynorm[k] = ||Y_k||^2 ; pad rows zeroed.
// One block per k (grid = KP), 128 threads, 4 d-values each (float4).
// ---------------------------------------------------------------------------
__global__ void y_kernel(const float* __restrict__ W) {
    int k = blockIdx.x;
    int t = threadIdx.x;
    if (k >= KLAT) {
        ((float4*)(g_Y + (size_t)k * DIM))[t] = make_float4(0.f, 0.f, 0.f, 0.f);
        if (t == 0) g_ynorm[k] = 0.0f;
        return;
    }
    __shared__ float phis[MRBF];
    __shared__ double red[128];
    if (t < MRBF) phis[t] = g_phi[k * MRBF + t];
    if (t + 128 < MRBF) phis[t + 128] = g_phi[k * MRBF + t + 128];
    __syncthreads();

    float4 acc = make_float4(0.f, 0.f, 0.f, 0.f);
    const float4* W4 = (const float4*)W;
    #pragma unroll 4
    for (int m = 0; m < MRBF; m++) {
        float p = phis[m];
        float4 w = W4[m * (DIM / 4) + t];
        acc.x += p * w.x; acc.y += p * w.y; acc.z += p * w.z; acc.w += p * w.w;
    }
    ((float4*)(g_Y + (size_t)k * DIM))[t] = acc;

    double ss = (double)acc.x * acc.x + (double)acc.y * acc.y +
                (double)acc.z * acc.z + (double)acc.w * acc.w;
    red[t] = ss;
    __syncthreads();
    for (int o = 64; o > 0; o >>= 1) {
        if (t < o) red[t] += red[t + o];
        __syncthreads();
    }
    if (t == 0) g_ynorm[k] = (float)red[0];
}

// ---------------------------------------------------------------------------
// Fused: S = t @ Y^T (64 rows x 384 k per block), softmax over k, write R.T,
// deterministic per-block log-sum partial.
// E'(k,n) = b*dot - (b/2)*ynorm[k]   (tnorm term cancels in exp-normalize)
// ---------------------------------------------------------------------------
__global__ void __launch_bounds__(512, 1)
gtm_main_kernel(const float* __restrict__ t_in, const float* __restrict__ beta,
                float* __restrict__ out, long long out_off) {
    __shared__ float Ys[KP][YSTRIDE];     // 384 x 20
    __shared__ float Ts[BM][YSTRIDE];     // 64 x 20
    __shared__ float red_max[8][2][8];
    __shared__ float red_sum[8][2][8];
    __shared__ double dred[64];

    const int tid = threadIdx.x;
    const int tx  = tid & 63;     // k-group lane (0..63)
    const int ty  = tid >> 6;     // n-group (0..7)
    const int lane = tid & 31;
    const int half = (tx >> 5);   // which 32-lane half of the 64 k-threads
    const long long n0 = (long long)blockIdx.x * BM;

    const float b  = beta[0];
    const float bh = 0.5f * b;

    float acc[8][6];
    #pragma unroll
    for (int j = 0; j < 8; j++)
        #pragma unroll
        for (int i = 0; i < 6; i++) acc[j][i] = 0.0f;

    const float* tbase = t_in + n0 * DIM;

    for (int dc = 0; dc < DIM; dc += DK) {
        // stage Y tile: 384 x 16 = 1536 float4, 3 per thread
        #pragma unroll
        for (int r = 0; r < 3; r++) {
            int idx = tid + r * 512;
            int k = idx >> 2;
            int q = idx & 3;
            float4 v = *(const float4*)(g_Y + (size_t)k * DIM + dc + q * 4);
            *(float4*)(&Ys[k][q * 4]) = v;
        }
        // stage t tile: 64 x 16 = 256 float4
        if (tid < 256) {
            int n = tid >> 2, q = tid & 3;
            float4 v = *(const float4*)(tbase + (size_t)n * DIM + dc + q * 4);
            *(float4*)(&Ts[n][q * 4]) = v;
        }
        __syncthreads();

        #pragma unroll
        for (int q = 0; q < 4; q++) {
            float4 tf[8], yf[6];
            #pragma unroll
            for (int j = 0; j < 8; j++)
                tf[j] = *(const float4*)(&Ts[j * 8 + ty][q * 4]);  // warp broadcast
            #pragma unroll
            for (int i = 0; i < 6; i++)
                yf[i] = *(const float4*)(&Ys[i * 64 + tx][q * 4]); // conflict-free
            #pragma unroll
            for (int j = 0; j < 8; j++)
                #pragma unroll
                for (int i = 0; i < 6; i++) {
                    acc[j][i] += tf[j].x * yf[i].x;
                    acc[j][i] += tf[j].y * yf[i].y;
                    acc[j][i] += tf[j].z * yf[i].z;
                    acc[j][i] += tf[j].w * yf[i].w;
                }
        }
        __syncthreads();
    }

    // ---- epilogue: E' = b*dot - bh*ynorm (pad k -> -1e30) ----
    float yn[6];
    #pragma unroll
    for (int i = 0; i < 6; i++) yn[i] = g_ynorm[i * 64 + tx];

    #pragma unroll
    for (int j = 0; j < 8; j++)
        #pragma unroll
        for (int i = 0; i < 6; i++) {
            bool valid = (i < 5) || (tx < (KLAT - 320));
            acc[j][i] = valid ? (b * acc[j][i] - bh * yn[i]) : -1e30f;
        }

    // row max over k (64 lanes x 6 each)
    float mx[8];
    #pragma unroll
    for (int j = 0; j < 8; j++) {
        float m = acc[j][0];
        #pragma unroll
        for (int i = 1; i < 6; i++) m = fmaxf(m, acc[j][i]);
        #pragma unroll
        for (int o = 16; o > 0; o >>= 1)
            m = fmaxf(m, __shfl_xor_sync(0xffffffffu, m, o));
        mx[j] = m;
    }
    if (lane == 0) {
        #pragma unroll
        for (int j = 0; j < 8; j++) red_max[ty][half][j] = mx[j];
    }
    __syncthreads();
    float rowmax[8];
    #pragma unroll
    for (int j = 0; j < 8; j++)
        rowmax[j] = fmaxf(red_max[ty][0][j], red_max[ty][1][j]);

    // exp + row sum
    float sm[8];
    #pragma unroll
    for (int j = 0; j < 8; j++) {
        float s = 0.0f;
        #pragma unroll
        for (int i = 0; i < 6; i++) {
            float p = expf(acc[j][i] - rowmax[j]);
            acc[j][i] = p;
            s += p;
        }
        #pragma unroll
        for (int o = 16; o > 0; o >>= 1)
            s += __shfl_xor_sync(0xffffffffu, s, o);
        sm[j] = s;
    }
    if (lane == 0) {
        #pragma unroll
        for (int j = 0; j < 8; j++) red_sum[ty][half][j] = sm[j];
    }
    __syncthreads();

    // normalize + store R.T rows (coalesced: k = i*64 + tx across lanes)
    #pragma unroll
    for (int j = 0; j < 8; j++) {
        float s = red_sum[ty][0][j] + red_sum[ty][1][j];
        float inv = 1.0f / s;
        long long n = n0 + j * 8 + ty;
        float* op = out + out_off + n * (long long)KLAT;
        #pragma unroll
        for (int i = 0; i < 6; i++) {
            int k = i * 64 + tx;
            if (k < KLAT) op[k] = acc[j][i] * inv;
        }
    }

    // deterministic ll partial: sum_{n in block} log(s_n)
    if (tid < 64) {
        int j = tid >> 3, ty_ = tid & 7;  // n_local == tid
        double s = (double)red_sum[ty_][0][j] + (double)red_sum[ty_][1][j];
        dred[tid] = log(s);
    }
    __syncthreads();
    for (int o = 32; o > 0; o >>= 1) {
        if (tid < o) dred[tid] += dred[tid + o];
        __syncthreads();
    }
    if (tid == 0) g_partial[blockIdx.x] = dred[0];
}

// ---------------------------------------------------------------------------
// Final reduce: ll = (N*(D/2*log(b/2pi) - log K) + sum log s) / N ; out[0]=-ll
// ---------------------------------------------------------------------------
__global__ void final_kernel(const float* __restrict__ beta,
                             float* __restrict__ out, int Nrows, int nblocks) {
    __shared__ double red[1024];
    int tid = threadIdx.x;
    double s = 0.0;
    for (int i = tid; i < nblocks; i += 1024) s += g_partial[i];
    red[tid] = s;
    __syncthreads();
    for (int o = 512; o > 0; o >>= 1) {
        if (tid < o) red[tid] += red[tid + o];
        __syncthreads();
    }
    if (tid == 0) {
        double b = (double)beta[0];
        double cst = 256.0 * log(b / (2.0 * M_PI)) - log(360.0);
        double ll = ((double)Nrows * cst + red[0]) / (double)Nrows;
        out[0] = (float)(-ll);
    }
}

// ---------------------------------------------------------------------------
extern "C" void kernel_launch(void* const* d_in, const int* in_sizes, int n_in,
                              void* d_out, int out_size) {
    const float* t    = (const float*)d_in[0];
    const float* W    = (const float*)d_in[1];
    const float* beta = (const float*)d_in[2];
    float* out = (float*)d_out;

    int N = in_sizes[0] / DIM;               // 131072
    long long off = (long long)out_size - (long long)N * KLAT;  // scalar slot(s) first
    if (off < 0) off = 0;

    phi_kernel<<<(KLAT * MRBF + 255) / 256, 256>>>();
    y_kernel<<<KP, 128>>>(W);
    int nblocks = N / BM;
    gtm_main_kernel<<<nblocks, 512>>>(t, beta, out, off);
    final_kernel<<<1, 1024>>>(beta, out, N, nblocks);
}

// round 2
// speedup vs baseline: 1.0706x; 1.0706x over previous
#include <cuda_runtime.h>
#include <math.h>
#include <float.h>

// Problem constants
#define DIM   512
#define KLAT  360      // latent nodes
#define KP    384      // padded K (multiple of 64)
#define MRBF  145      // 12*12 + 1 bias
#define BM    64       // rows of t per block
#define DK    16       // d-chunk
#define YSTRIDE (DK + 4)   // 20 -> conflict-free float4 LDS
#define TSTRIDE 68         // padded transposed-t row stride (floats)

// Scratch (device globals; no allocation allowed)
__device__ float  g_phi[KLAT * MRBF];
__device__ float  g_Y[KP * DIM];        // Y[k][d], rows 360..383 zero
__device__ float  g_ynorm[KP];
__device__ double g_partial[4096];      // per-block log-sum partials

// packed f32x2 helpers -------------------------------------------------------
__device__ __forceinline__ void fma_f32x2(double& acc, double a, double b) {
    asm("fma.rn.f32x2 %0, %1, %2, %0;" : "+d"(acc) : "d"(a), "d"(b));
}
__device__ __forceinline__ double dup_f32(float v) {
    double r;
    asm("mov.b64 %0, {%1, %1};" : "=d"(r) : "f"(v));
    return r;
}
__device__ __forceinline__ float lo_f32(double v) {
    float r; asm("{ .reg .f32 hi; mov.b64 {%0, hi}, %1; }" : "=f"(r) : "d"(v));
    return r;
}
__device__ __forceinline__ float hi_f32(double v) {
    float r; asm("{ .reg .f32 lo; mov.b64 {lo, %0}, %1; }" : "=f"(r) : "d"(v));
    return r;
}

// ---------------------------------------------------------------------------
// phi[k][m] = exp(-3 * ||x_k - c_m||^2)
// ---------------------------------------------------------------------------
__global__ void phi_kernel() {
    int idx = blockIdx.x * blockDim.x + threadIdx.x;
    if (idx >= KLAT * MRBF) return;
    int k = idx / MRBF, m = idx % MRBF;
    float val;
    if (m == MRBF - 1) {
        val = 1.0f;  // bias column
    } else {
        int ia = k / 18, ib = k % 18;
        double x0 = -1.0 + ia * (2.0 / 19.0);
        double x1 = -1.0 + ib * (2.0 / 17.0);
        int mi = m / 12, mj = m % 12;
        double step = (2.0 - 2.0 / 12.0) / 11.0;
        double c0 = -1.0 + 1.0 / 12.0 + mi * step;
        double c1 = -1.0 + 1.0 / 12.0 + mj * step;
        double d2 = (x0 - c0) * (x0 - c0) + (x1 - c1) * (x1 - c1);
        val = (float)exp(-3.0 * d2);
    }
    g_phi[idx] = val;
}

// ---------------------------------------------------------------------------
// Y = phi @ W  (360x512), ynorm[k] = ||Y_k||^2 ; pad rows zeroed.
// ---------------------------------------------------------------------------
__global__ void y_kernel(const float* __restrict__ W) {
    int k = blockIdx.x;
    int t = threadIdx.x;
    if (k >= KLAT) {
        ((float4*)(g_Y + (size_t)k * DIM))[t] = make_float4(0.f, 0.f, 0.f, 0.f);
        if (t == 0) g_ynorm[k] = 0.0f;
        return;
    }
    __shared__ float phis[MRBF];
    __shared__ double red[128];
    if (t < MRBF) phis[t] = g_phi[k * MRBF + t];
    if (t + 128 < MRBF) phis[t + 128] = g_phi[k * MRBF + t + 128];
    __syncthreads();

    float4 acc = make_float4(0.f, 0.f, 0.f, 0.f);
    const float4* W4 = (const float4*)W;
    #pragma unroll 4
    for (int m = 0; m < MRBF; m++) {
        float p = phis[m];
        float4 w = W4[m * (DIM / 4) + t];
        acc.x += p * w.x; acc.y += p * w.y; acc.z += p * w.z; acc.w += p * w.w;
    }
    ((float4*)(g_Y + (size_t)k * DIM))[t] = acc;

    double ss = (double)acc.x * acc.x + (double)acc.y * acc.y +
                (double)acc.z * acc.z + (double)acc.w * acc.w;
    red[t] = ss;
    __syncthreads();
    for (int o = 64; o > 0; o >>= 1) {
        if (t < o) red[t] += red[t + o];
        __syncthreads();
    }
    if (t == 0) g_ynorm[k] = (float)red[0];
}

// ---------------------------------------------------------------------------
// Fused main: S = t @ Y^T via packed f32x2 FMA, softmax over k, write R.T.
// Accumulator pairs over adjacent n-rows (j = 2p, 2p+1); t-pairs come from a
// transposed+permuted t tile as 8-byte broadcasts; Y operand is duplicated.
// E'(k,n) = b*dot - (b/2)*ynorm[k]   (tnorm term cancels in exp-normalize)
// ---------------------------------------------------------------------------
__global__ void __launch_bounds__(512, 1)
gtm_main_kernel(const float* __restrict__ t_in, const float* __restrict__ beta,
                float* __restrict__ out, long long out_off) {
    __shared__ __align__(16) float Ys[KP][YSTRIDE];   // 384 x 20
    __shared__ __align__(16) float TsT[DK][TSTRIDE];  // 16 x 68 (transposed t)
    __shared__ float red_max[8][2][8];
    __shared__ float red_sum[8][2][8];
    __shared__ double dred[64];

    const int tid = threadIdx.x;
    const int tx  = tid & 63;     // k-group lane (0..63)
    const int ty  = tid >> 6;     // n-group (0..7)
    const int lane = tid & 31;
    const int half = (tx >> 5);
    const long long n0 = (long long)blockIdx.x * BM;

    const float b  = beta[0];
    const float bh = 0.5f * b;

    // acc2[p][i] packs rows j=2p (lo) and j=2p+1 (hi), logical n = j*8+ty
    double acc2[4][6];
    #pragma unroll
    for (int p = 0; p < 4; p++)
        #pragma unroll
        for (int i = 0; i < 6; i++) acc2[p][i] = 0.0;

    const float* tbase = t_in + n0 * DIM;

    for (int dc = 0; dc < DIM; dc += DK) {
        // stage Y tile: 384 x 16 = 1536 float4, 3 per thread
        #pragma unroll
        for (int r = 0; r < 3; r++) {
            int idx = tid + r * 512;
            int k = idx >> 2;
            int q = idx & 3;
            float4 v = *(const float4*)(g_Y + (size_t)k * DIM + dc + q * 4);
            *(float4*)(&Ys[k][q * 4]) = v;
        }
        // stage transposed t tile: slot(n) = (n&7)*8 + (n>>3)
        // -> pairs (j=2p, 2p+1) at fixed ty are adjacent: col = ty*8 + j
        if (tid < 256) {
            int n = tid >> 2, q = tid & 3;
            float4 v = *(const float4*)(tbase + (size_t)n * DIM + dc + q * 4);
            int slot = ((n & 7) << 3) | (n >> 3);
            TsT[q * 4 + 0][slot] = v.x;
            TsT[q * 4 + 1][slot] = v.y;
            TsT[q * 4 + 2][slot] = v.z;
            TsT[q * 4 + 3][slot] = v.w;
        }
        __syncthreads();

        #pragma unroll
        for (int q = 0; q < 4; q++) {
            float yfa[6][4];
            #pragma unroll
            for (int i = 0; i < 6; i++) {
                float4 v = *(const float4*)(&Ys[i * 64 + tx][q * 4]);
                yfa[i][0] = v.x; yfa[i][1] = v.y; yfa[i][2] = v.z; yfa[i][3] = v.w;
            }
            #pragma unroll
            for (int c = 0; c < 4; c++) {
                double yp[6];
                #pragma unroll
                for (int i = 0; i < 6; i++) yp[i] = dup_f32(yfa[i][c]);
                #pragma unroll
                for (int p = 0; p < 4; p++) {
                    double tp = *(const double*)(&TsT[q * 4 + c][ty * 8 + 2 * p]);
                    #pragma unroll
                    for (int i = 0; i < 6; i++) fma_f32x2(acc2[p][i], tp, yp[i]);
                }
            }
        }
        __syncthreads();
    }

    // unpack to round-1 layout: acc[j][i], j = row group (n = j*8 + ty)
    float acc[8][6];
    #pragma unroll
    for (int p = 0; p < 4; p++)
        #pragma unroll
        for (int i = 0; i < 6; i++) {
            acc[2 * p + 0][i] = lo_f32(acc2[p][i]);
            acc[2 * p + 1][i] = hi_f32(acc2[p][i]);
        }

    // ---- epilogue: E' = b*dot - bh*ynorm (pad k -> -1e30) ----
    float yn[6];
    #pragma unroll
    for (int i = 0; i < 6; i++) yn[i] = g_ynorm[i * 64 + tx];

    #pragma unroll
    for (int j = 0; j < 8; j++)
        #pragma unroll
        for (int i = 0; i < 6; i++) {
            bool valid = (i < 5) || (tx < (KLAT - 320));
            acc[j][i] = valid ? (b * acc[j][i] - bh * yn[i]) : -1e30f;
        }

    // row max over k
    float mx[8];
    #pragma unroll
    for (int j = 0; j < 8; j++) {
        float m = acc[j][0];
        #pragma unroll
        for (int i = 1; i < 6; i++) m = fmaxf(m, acc[j][i]);
        #pragma unroll
        for (int o = 16; o > 0; o >>= 1)
            m = fmaxf(m, __shfl_xor_sync(0xffffffffu, m, o));
        mx[j] = m;
    }
    if (lane == 0) {
        #pragma unroll
        for (int j = 0; j < 8; j++) red_max[ty][half][j] = mx[j];
    }
    __syncthreads();
    float rowmax[8];
    #pragma unroll
    for (int j = 0; j < 8; j++)
        rowmax[j] = fmaxf(red_max[ty][0][j], red_max[ty][1][j]);

    // exp + row sum
    float sm[8];
    #pragma unroll
    for (int j = 0; j < 8; j++) {
        float s = 0.0f;
        #pragma unroll
        for (int i = 0; i < 6; i++) {
            float p = expf(acc[j][i] - rowmax[j]);
            acc[j][i] = p;
            s += p;
        }
        #pragma unroll
        for (int o = 16; o > 0; o >>= 1)
            s += __shfl_xor_sync(0xffffffffu, s, o);
        sm[j] = s;
    }
    if (lane == 0) {
        #pragma unroll
        for (int j = 0; j < 8; j++) red_sum[ty][half][j] = sm[j];
    }
    __syncthreads();

    // normalize + store R.T rows (coalesced over k)
    #pragma unroll
    for (int j = 0; j < 8; j++) {
        float s = red_sum[ty][0][j] + red_sum[ty][1][j];
        float inv = 1.0f / s;
        long long n = n0 + j * 8 + ty;
        float* op = out + out_off + n * (long long)KLAT;
        #pragma unroll
        for (int i = 0; i < 6; i++) {
            int k = i * 64 + tx;
            if (k < KLAT) op[k] = acc[j][i] * inv;
        }
    }

    // deterministic ll partial: sum_{n in block} log(s_n)
    if (tid < 64) {
        int j = tid >> 3, ty_ = tid & 7;
        double s = (double)red_sum[ty_][0][j] + (double)red_sum[ty_][1][j];
        dred[tid] = log(s);
    }
    __syncthreads();
    for (int o = 32; o > 0; o >>= 1) {
        if (tid < o) dred[tid] += dred[tid + o];
        __syncthreads();
    }
    if (tid == 0) g_partial[blockIdx.x] = dred[0];
}

// ---------------------------------------------------------------------------
// Final reduce: ll = (N*(D/2*log(b/2pi) - log K) + sum log s) / N ; out[0]=-ll
// ---------------------------------------------------------------------------
__global__ void final_kernel(const float* __restrict__ beta,
                             float* __restrict__ out, int Nrows, int nblocks) {
    __shared__ double red[1024];
    int tid = threadIdx.x;
    double s = 0.0;
    for (int i = tid; i < nblocks; i += 1024) s += g_partial[i];
    red[tid] = s;
    __syncthreads();
    for (int o = 512; o > 0; o >>= 1) {
        if (tid < o) red[tid] += red[tid + o];
        __syncthreads();
    }
    if (tid == 0) {
        double b = (double)beta[0];
        double cst = 256.0 * log(b / (2.0 * M_PI)) - log(360.0);
        double ll = ((double)Nrows * cst + red[0]) / (double)Nrows;
        out[0] = (float)(-ll);
    }
}

// ---------------------------------------------------------------------------
extern "C" void kernel_launch(void* const* d_in, const int* in_sizes, int n_in,
                              void* d_out, int out_size) {
    const float* t    = (const float*)d_in[0];
    const float* W    = (const float*)d_in[1];
    const float* beta = (const float*)d_in[2];
    float* out = (float*)d_out;

    int N = in_sizes[0] / DIM;               // 131072
    long long off = (long long)out_size - (long long)N * KLAT;
    if (off < 0) off = 0;

    phi_kernel<<<(KLAT * MRBF + 255) / 256, 256>>>();
    y_kernel<<<KP, 128>>>(W);
    int nblocks = N / BM;
    gtm_main_kernel<<<nblocks, 512>>>(t, beta, out, off);
    final_kernel<<<1, 1024>>>(beta, out, N, nblocks);
}

// round 4
// speedup vs baseline: 2.1091x; 1.9700x over previous
#include <cuda_runtime.h>
#include <cuda_fp16.h>
#include <math.h>
#include <float.h>
#include <stdint.h>

// ---------------------------------------------------------------------------
// Problem constants
// ---------------------------------------------------------------------------
#define DIM    512
#define KLAT   360
#define KP     384          // padded K
#define MRBF   145
#define TM     128          // t-rows per CTA
#define DC     64           // D-chunk in elements (128 B of halves per row)
#define NCHUNK (DIM / DC)   // 8
#define NTHREADS 512

// SMEM layout (dynamic, phases overlap)
#define OFF_AHI   0                       // 128 x 128B = 16384
#define OFF_ALO   16384
#define OFF_BHI   32768                   // 384 x 128B = 49152
#define OFF_BLO   81920                   // ends 131072
#define OFF_STAGE 0                       // epilogue reuse
#define STAGE_STRIDE 396                  // floats; 396*4=1584 mod128=48 -> conflict-free
#define OFF_REDM  202752                  // 4*128 floats
#define OFF_REDS  204800                  // 4*128 floats
#define OFF_YN    206848                  // 384 floats
#define SMEM_TOTAL 208896

// Scratch (device globals; no allocation allowed)
__device__ float  g_phi[KLAT * MRBF];
__device__ float  g_ynorm[KP];
__device__ __half g_Yhi[KP * DIM];
__device__ __half g_Ylo[KP * DIM];
__device__ double g_partial[4096];

// ---------------------------------------------------------------------------
// helpers
// ---------------------------------------------------------------------------
__device__ __forceinline__ uint32_t smem_u32(const void* p) {
    uint32_t a;
    asm("{ .reg .u64 t; cvta.to.shared.u64 t, %1; cvt.u32.u64 %0, t; }"
        : "=r"(a) : "l"(p));
    return a;
}
__device__ __forceinline__ uint32_t swz(uint32_t off) {
    return off ^ ((off >> 3) & 0x70);
}
__device__ __forceinline__ void ldsm_x4(uint32_t* r, uint32_t addr) {
    asm volatile("ldmatrix.sync.aligned.m8n8.x4.shared.b16 {%0,%1,%2,%3}, [%4];"
                 : "=r"(r[0]), "=r"(r[1]), "=r"(r[2]), "=r"(r[3]) : "r"(addr));
}
__device__ __forceinline__ void mma16816(float* c, const uint32_t* a,
                                         uint32_t b0, uint32_t b1) {
    asm volatile("mma.sync.aligned.m16n8k16.row.col.f32.f16.f16.f32 "
                 "{%0,%1,%2,%3}, {%4,%5,%6,%7}, {%8,%9}, {%0,%1,%2,%3};"
                 : "+f"(c[0]), "+f"(c[1]), "+f"(c[2]), "+f"(c[3])
                 : "r"(a[0]), "r"(a[1]), "r"(a[2]), "r"(a[3]), "r"(b0), "r"(b1));
}

// ---------------------------------------------------------------------------
// phi[k][m] = exp(-3 * ||x_k - c_m||^2)
// ---------------------------------------------------------------------------
__global__ void phi_kernel() {
    int idx = blockIdx.x * blockDim.x + threadIdx.x;
    if (idx >= KLAT * MRBF) return;
    int k = idx / MRBF, m = idx % MRBF;
    float val;
    if (m == MRBF - 1) {
        val = 1.0f;
    } else {
        int ia = k / 18, ib = k % 18;
        double x0 = -1.0 + ia * (2.0 / 19.0);
        double x1 = -1.0 + ib * (2.0 / 17.0);
        int mi = m / 12, mj = m % 12;
        double step = (2.0 - 2.0 / 12.0) / 11.0;
        double c0 = -1.0 + 1.0 / 12.0 + mi * step;
        double c1 = -1.0 + 1.0 / 12.0 + mj * step;
        double d2 = (x0 - c0) * (x0 - c0) + (x1 - c1) * (x1 - c1);
        val = (float)exp(-3.0 * d2);
    }
    g_phi[idx] = val;
}

// ---------------------------------------------------------------------------
// Y = phi @ W ; emit fp16 hi/lo split + ynorm. Pad rows zero.
// ---------------------------------------------------------------------------
__global__ void y_kernel(const float* __restrict__ W) {
    int k = blockIdx.x;
    int t = threadIdx.x;   // 128 threads, 4 cols each
    if (k >= KLAT) {
        #pragma unroll
        for (int i = 0; i < 4; i++) {
            g_Yhi[(size_t)k * DIM + t * 4 + i] = __float2half(0.f);
            g_Ylo[(size_t)k * DIM + t * 4 + i] = __float2half(0.f);
        }
        if (t == 0) g_ynorm[k] = 0.0f;
        return;
    }
    __shared__ float phis[MRBF];
    __shared__ double red[128];
    if (t < MRBF) phis[t] = g_phi[k * MRBF + t];
    if (t + 128 < MRBF) phis[t + 128] = g_phi[k * MRBF + t + 128];
    __syncthreads();

    float4 acc = make_float4(0.f, 0.f, 0.f, 0.f);
    const float4* W4 = (const float4*)W;
    #pragma unroll 4
    for (int m = 0; m < MRBF; m++) {
        float p = phis[m];
        float4 w = W4[m * (DIM / 4) + t];
        acc.x += p * w.x; acc.y += p * w.y; acc.z += p * w.z; acc.w += p * w.w;
    }
    float a[4] = {acc.x, acc.y, acc.z, acc.w};
    #pragma unroll
    for (int i = 0; i < 4; i++) {
        __half h = __float2half_rn(a[i]);
        __half l = __float2half_rn(a[i] - __half2float(h));
        g_Yhi[(size_t)k * DIM + t * 4 + i] = h;
        g_Ylo[(size_t)k * DIM + t * 4 + i] = l;
    }
    double ss = (double)acc.x * acc.x + (double)acc.y * acc.y +
                (double)acc.z * acc.z + (double)acc.w * acc.w;
    red[t] = ss;
    __syncthreads();
    for (int o = 64; o > 0; o >>= 1) {
        if (t < o) red[t] += red[t + o];
        __syncthreads();
    }
    if (t == 0) g_ynorm[k] = (float)red[0];
}

__global__ void noop_kernel() {}

// ---------------------------------------------------------------------------
// Main fused kernel: S = t @ Y^T via mma.sync f16 3-pass split (HMMA),
// softmax over k, coalesced R.T store, deterministic ll partials.
// Warp grid 4x4, warp tile 32 (m) x 96 (n), acc fp32 in registers.
// ---------------------------------------------------------------------------
__global__ void __launch_bounds__(NTHREADS, 1)
gtm_mma_kernel(const float* __restrict__ t_in, const float* __restrict__ beta,
               float* __restrict__ out, long long out_off) {
    extern __shared__ char smem[];
    const uint32_t sbase = smem_u32(smem);
    const int tid  = threadIdx.x;
    const int lane = tid & 31;
    const int wid  = tid >> 5;
    const int wr   = wid >> 2;   // warp row (0..3): rows wr*32..wr*32+31
    const int wc   = wid & 3;    // warp col (0..3): cols wc*96..wc*96+95
    const long long n0 = (long long)blockIdx.x * TM;

    float* yns = (float*)(smem + OFF_YN);
    if (tid < KP) yns[tid] = g_ynorm[tid];

    const float b  = beta[0];
    const float bh = 0.5f * b;

    // acc[mt][j][c]: m-tile (16 rows), n8-tile j (0..11), frag reg c
    float acc[2][12][4];
    #pragma unroll
    for (int mt = 0; mt < 2; mt++)
        #pragma unroll
        for (int j = 0; j < 12; j++)
            #pragma unroll
            for (int c = 0; c < 4; c++) acc[mt][j][c] = 0.0f;

    // per-thread ldmatrix row offsets (pre-swizzle)
    uint32_t rA[2], rB[6];
    #pragma unroll
    for (int mt = 0; mt < 2; mt++)
        rA[mt] = (uint32_t)((wr * 32 + mt * 16 + (lane & 15)) * 128 + ((lane >> 4) << 4));
    #pragma unroll
    for (int j6 = 0; j6 < 6; j6++)
        rB[j6] = (uint32_t)((wc * 96 + j6 * 16 + (lane & 15)) * 128 + ((lane >> 4) << 4));

    const uint32_t ahi_b = sbase + OFF_AHI;
    const uint32_t alo_b = sbase + OFF_ALO;
    const uint32_t bhi_b = sbase + OFF_BHI;
    const uint32_t blo_b = sbase + OFF_BLO;

    // A staging role: one 16-float segment per thread
    const int arow = tid >> 2;
    const int aseg = tid & 3;
    const float* asrc = t_in + (n0 + arow) * (long long)DIM + aseg * 16;
    const uint32_t aoff = (uint32_t)(arow * 128 + aseg * 32);
    const uint4* Yhi4 = (const uint4*)g_Yhi;   // row stride 64 uint4
    const uint4* Ylo4 = (const uint4*)g_Ylo;

    for (int ci = 0; ci < NCHUNK; ci++) {
        // ---- stage A (t chunk) with fp16 split ----
        {
            __align__(16) __half hi[16], lo[16];
            #pragma unroll
            for (int q = 0; q < 4; q++) {
                float4 v = *(const float4*)(asrc + ci * DC + q * 4);
                float x[4] = {v.x, v.y, v.z, v.w};
                #pragma unroll
                for (int e = 0; e < 4; e++) {
                    __half h = __float2half_rn(x[e]);
                    hi[q * 4 + e] = h;
                    lo[q * 4 + e] = __float2half_rn(x[e] - __half2float(h));
                }
            }
            *(uint4*)(smem + OFF_AHI + swz(aoff))      = ((uint4*)hi)[0];
            *(uint4*)(smem + OFF_AHI + swz(aoff + 16)) = ((uint4*)hi)[1];
            *(uint4*)(smem + OFF_ALO + swz(aoff))      = ((uint4*)lo)[0];
            *(uint4*)(smem + OFF_ALO + swz(aoff + 16)) = ((uint4*)lo)[1];
        }
        // ---- stage B (Y chunk, pre-split in global) ----
        #pragma unroll
        for (int s = 0; s < 6; s++) {
            int idx = tid + s * 512;
            int r = idx >> 3, u = idx & 7;
            uint32_t o = swz((uint32_t)(r * 128 + u * 16));
            *(uint4*)(smem + OFF_BHI + o) = Yhi4[r * 64 + ci * 8 + u];
            *(uint4*)(smem + OFF_BLO + o) = Ylo4[r * 64 + ci * 8 + u];
        }
        __syncthreads();

        #pragma unroll
        for (int ks = 0; ks < 4; ks++) {
            const uint32_t ko = (uint32_t)(ks * 32);
            uint32_t a[2][4];
            ldsm_x4(a[0], ahi_b + swz(rA[0] + ko));
            ldsm_x4(a[1], ahi_b + swz(rA[1] + ko));
            // passes 1 (hi*hi) and 2 (hi*lo)
            #pragma unroll
            for (int j6 = 0; j6 < 6; j6++) {
                uint32_t bf[4];
                ldsm_x4(bf, bhi_b + swz(rB[j6] + ko));
                #pragma unroll
                for (int mt = 0; mt < 2; mt++) {
                    mma16816(acc[mt][2 * j6 + 0], a[mt], bf[0], bf[2]);
                    mma16816(acc[mt][2 * j6 + 1], a[mt], bf[1], bf[3]);
                }
                ldsm_x4(bf, blo_b + swz(rB[j6] + ko));
                #pragma unroll
                for (int mt = 0; mt < 2; mt++) {
                    mma16816(acc[mt][2 * j6 + 0], a[mt], bf[0], bf[2]);
                    mma16816(acc[mt][2 * j6 + 1], a[mt], bf[1], bf[3]);
                }
            }
            // pass 3 (lo*hi) — overwrite A frags, reload B hi
            ldsm_x4(a[0], alo_b + swz(rA[0] + ko));
            ldsm_x4(a[1], alo_b + swz(rA[1] + ko));
            #pragma unroll
            for (int j6 = 0; j6 < 6; j6++) {
                uint32_t bf[4];
                ldsm_x4(bf, bhi_b + swz(rB[j6] + ko));
                #pragma unroll
                for (int mt = 0; mt < 2; mt++) {
                    mma16816(acc[mt][2 * j6 + 0], a[mt], bf[0], bf[2]);
                    mma16816(acc[mt][2 * j6 + 1], a[mt], bf[1], bf[3]);
                }
            }
        }
        __syncthreads();
    }

    // ------------------------- epilogue -------------------------
    float* stage = (float*)(smem + OFF_STAGE);
    float* redm  = (float*)(smem + OFF_REDM);
    float* reds  = (float*)(smem + OFF_REDS);

    const int colb = wc * 96 + (lane & 3) * 2;

    // E = b*dot - bh*ynorm[col], mask col >= KLAT
    #pragma unroll
    for (int j = 0; j < 12; j++) {
        int c0 = colb + j * 8;
        float y0 = yns[c0], y1 = yns[c0 + 1];
        bool v0 = (c0 < KLAT), v1 = (c0 + 1 < KLAT);
        #pragma unroll
        for (int mt = 0; mt < 2; mt++) {
            #pragma unroll
            for (int h = 0; h < 2; h++) {
                float e0 = b * acc[mt][j][2 * h]     - bh * y0;
                float e1 = b * acc[mt][j][2 * h + 1] - bh * y1;
                acc[mt][j][2 * h]     = v0 ? e0 : -1e30f;
                acc[mt][j][2 * h + 1] = v1 ? e1 : -1e30f;
            }
        }
    }

    // row max (per warp, 4-lane groups share a row)
    #pragma unroll
    for (int mt = 0; mt < 2; mt++)
        #pragma unroll
        for (int h = 0; h < 2; h++) {
            float m = -FLT_MAX;
            #pragma unroll
            for (int j = 0; j < 12; j++)
                m = fmaxf(m, fmaxf(acc[mt][j][2 * h], acc[mt][j][2 * h + 1]));
            m = fmaxf(m, __shfl_xor_sync(0xffffffffu, m, 1));
            m = fmaxf(m, __shfl_xor_sync(0xffffffffu, m, 2));
            if ((lane & 3) == 0) {
                int row = wr * 32 + mt * 16 + h * 8 + (lane >> 2);
                redm[wc * 128 + row] = m;
            }
        }
    __syncthreads();

    float M[2][2], S[2][2];
    #pragma unroll
    for (int mt = 0; mt < 2; mt++)
        #pragma unroll
        for (int h = 0; h < 2; h++) {
            int row = wr * 32 + mt * 16 + h * 8 + (lane >> 2);
            M[mt][h] = fmaxf(fmaxf(redm[row], redm[128 + row]),
                             fmaxf(redm[256 + row], redm[384 + row]));
        }

    // exp + row sum (acc becomes p)
    #pragma unroll
    for (int mt = 0; mt < 2; mt++)
        #pragma unroll
        for (int h = 0; h < 2; h++) {
            float s = 0.0f;
            #pragma unroll
            for (int j = 0; j < 12; j++) {
                float p0 = __expf(acc[mt][j][2 * h]     - M[mt][h]);
                float p1 = __expf(acc[mt][j][2 * h + 1] - M[mt][h]);
                acc[mt][j][2 * h] = p0; acc[mt][j][2 * h + 1] = p1;
                s += p0 + p1;
            }
            s += __shfl_xor_sync(0xffffffffu, s, 1);
            s += __shfl_xor_sync(0xffffffffu, s, 2);
            if ((lane & 3) == 0) {
                int row = wr * 32 + mt * 16 + h * 8 + (lane >> 2);
                reds[wc * 128 + row] = s;
            }
        }
    __syncthreads();

    #pragma unroll
    for (int mt = 0; mt < 2; mt++)
        #pragma unroll
        for (int h = 0; h < 2; h++) {
            int row = wr * 32 + mt * 16 + h * 8 + (lane >> 2);
            S[mt][h] = reds[row] + reds[128 + row] + reds[256 + row] + reds[384 + row];
        }

    // normalized responsibilities -> stage (for coalesced output)
    #pragma unroll
    for (int mt = 0; mt < 2; mt++)
        #pragma unroll
        for (int h = 0; h < 2; h++) {
            int row = wr * 32 + mt * 16 + h * 8 + (lane >> 2);
            float inv = 1.0f / S[mt][h];
            float* srow = stage + row * STAGE_STRIDE;
            #pragma unroll
            for (int j = 0; j < 12; j++) {
                int c0 = colb + j * 8;
                if (c0 < KLAT)     srow[c0]     = acc[mt][j][2 * h] * inv;
                if (c0 + 1 < KLAT) srow[c0 + 1] = acc[mt][j][2 * h + 1] * inv;
            }
        }
    __syncthreads();

    // deterministic ll partial (warp 0)
    if (tid < 32) {
        double a = 0.0;
        #pragma unroll
        for (int i = 0; i < 4; i++) {
            int r = lane + i * 32;
            double st = (double)reds[r] + (double)reds[128 + r] +
                        (double)reds[256 + r] + (double)reds[384 + r];
            a += log(st);
        }
        #pragma unroll
        for (int o = 16; o > 0; o >>= 1)
            a += __shfl_xor_sync(0xffffffffu, a, o);
        if (lane == 0) g_partial[blockIdx.x] = a;
    }

    // coalesced store of R.T rows
    #pragma unroll
    for (int i = 0; i < 8; i++) {
        int r = wid + i * 16;
        const float* srow = stage + r * STAGE_STRIDE;
        float* orow = out + out_off + (n0 + r) * (long long)KLAT;
        #pragma unroll
        for (int s = 0; s < 12; s++) {
            int k = s * 32 + lane;
            if (k < KLAT) orow[k] = srow[k];
        }
    }
}

// ---------------------------------------------------------------------------
// Final reduce: out[0] = -ll
// ---------------------------------------------------------------------------
__global__ void final_kernel(const float* __restrict__ beta,
                             float* __restrict__ out, int Nrows, int nblocks) {
    __shared__ double red[1024];
    int tid = threadIdx.x;
    double s = 0.0;
    for (int i = tid; i < nblocks; i += 1024) s += g_partial[i];
    red[tid] = s;
    __syncthreads();
    for (int o = 512; o > 0; o >>= 1) {
        if (tid < o) red[tid] += red[tid + o];
        __syncthreads();
    }
    if (tid == 0) {
        double b = (double)beta[0];
        double cst = 256.0 * log(b / (2.0 * M_PI)) - log(360.0);
        double ll = ((double)Nrows * cst + red[0]) / (double)Nrows;
        out[0] = (float)(-ll);
    }
}

// ---------------------------------------------------------------------------
extern "C" void kernel_launch(void* const* d_in, const int* in_sizes, int n_in,
                              void* d_out, int out_size) {
    const float* t    = (const float*)d_in[0];
    const float* W    = (const float*)d_in[1];
    const float* beta = (const float*)d_in[2];
    float* out = (float*)d_out;

    int N = in_sizes[0] / DIM;                                  // 131072
    long long off = (long long)out_size - (long long)N * KLAT;  // scalar slot first
    if (off < 0) off = 0;

    static int smem_set = 0;
    if (!smem_set) {
        cudaFuncSetAttribute(gtm_mma_kernel,
                             cudaFuncAttributeMaxDynamicSharedMemorySize, SMEM_TOTAL);
        smem_set = 1;
    }

    phi_kernel<<<(KLAT * MRBF + 255) / 256, 256>>>();
    y_kernel<<<KP, 128>>>(W);
    noop_kernel<<<1, 32>>>();
    int ntiles = N / TM;        // 1024
    gtm_mma_kernel<<<ntiles, NTHREADS, SMEM_TOTAL>>>(t, beta, out, off);
    final_kernel<<<1, 1024>>>(beta, out, N, ntiles);
}

// round 5
// speedup vs baseline: 2.4955x; 1.1832x over previous
#include <cuda_runtime.h>
#include <cuda_fp16.h>
#include <math.h>
#include <float.h>
#include <stdint.h>

// ---------------------------------------------------------------------------
// Problem constants
// ---------------------------------------------------------------------------
#define DIM    512
#define KLAT   360
#define KP     384          // padded K
#define MRBF   145
#define TM     128          // t-rows per CTA
#define DC     64           // D-chunk in elements (128 B of halves per row)
#define NCHUNK (DIM / DC)   // 8
#define NTHREADS 512

// SMEM layout (dynamic, phases overlap)
#define OFF_AHI   0                       // 128 x 128B = 16384
#define OFF_ALO   16384
#define OFF_BHI   32768                   // 384 x 128B = 49152
#define OFF_BLO   81920                   // ends 131072
#define OFF_STAGE 0                       // epilogue reuse
#define STAGE_STRIDE 396                  // floats; conflict-free
#define OFF_REDM  202752                  // 4*128 floats
#define OFF_REDS  204800                  // 4*128 floats
#define OFF_YN    206848                  // 384 floats
#define SMEM_TOTAL 208896

// Scratch (device globals; no allocation allowed)
__device__ float  g_phi[KLAT * MRBF];
__device__ float  g_ynorm[KP];
__device__ __half g_Yhi[KP * DIM];
__device__ __half g_Ylo[KP * DIM];
__device__ double g_partial[4096];

// ---------------------------------------------------------------------------
// helpers
// ---------------------------------------------------------------------------
__device__ __forceinline__ uint32_t smem_u32(const void* p) {
    uint32_t a;
    asm("{ .reg .u64 t; cvta.to.shared.u64 t, %1; cvt.u32.u64 %0, t; }"
        : "=r"(a) : "l"(p));
    return a;
}
__device__ __forceinline__ uint32_t swz(uint32_t off) {
    return off ^ ((off >> 3) & 0x70);
}
__device__ __forceinline__ void ldsm_x4(uint32_t* r, uint32_t addr) {
    asm volatile("ldmatrix.sync.aligned.m8n8.x4.shared.b16 {%0,%1,%2,%3}, [%4];"
                 : "=r"(r[0]), "=r"(r[1]), "=r"(r[2]), "=r"(r[3]) : "r"(addr));
}
__device__ __forceinline__ void mma16816(float* c, const uint32_t* a,
                                         uint32_t b0, uint32_t b1) {
    asm volatile("mma.sync.aligned.m16n8k16.row.col.f32.f16.f16.f32 "
                 "{%0,%1,%2,%3}, {%4,%5,%6,%7}, {%8,%9}, {%0,%1,%2,%3};"
                 : "+f"(c[0]), "+f"(c[1]), "+f"(c[2]), "+f"(c[3])
                 : "r"(a[0]), "r"(a[1]), "r"(a[2]), "r"(a[3]), "r"(b0), "r"(b1));
}
__device__ __forceinline__ void cp_async16(uint32_t dst, const void* src) {
    asm volatile("cp.async.cg.shared.global [%0], [%1], 16;"
                 :: "r"(dst), "l"(src) : "memory");
}
#define CP_COMMIT() asm volatile("cp.async.commit_group;" ::: "memory")
#define CP_WAIT0()  asm volatile("cp.async.wait_group 0;" ::: "memory")

// ---------------------------------------------------------------------------
// phi[k][m] = exp(-3 * ||x_k - c_m||^2)
// ---------------------------------------------------------------------------
__global__ void phi_kernel() {
    int idx = blockIdx.x * blockDim.x + threadIdx.x;
    if (idx >= KLAT * MRBF) return;
    int k = idx / MRBF, m = idx % MRBF;
    float val;
    if (m == MRBF - 1) {
        val = 1.0f;
    } else {
        int ia = k / 18, ib = k % 18;
        double x0 = -1.0 + ia * (2.0 / 19.0);
        double x1 = -1.0 + ib * (2.0 / 17.0);
        int mi = m / 12, mj = m % 12;
        double step = (2.0 - 2.0 / 12.0) / 11.0;
        double c0 = -1.0 + 1.0 / 12.0 + mi * step;
        double c1 = -1.0 + 1.0 / 12.0 + mj * step;
        double d2 = (x0 - c0) * (x0 - c0) + (x1 - c1) * (x1 - c1);
        val = (float)exp(-3.0 * d2);
    }
    g_phi[idx] = val;
}

// ---------------------------------------------------------------------------
// Y = phi @ W ; emit fp16 hi/lo split + ynorm. Pad rows zero.
// ---------------------------------------------------------------------------
__global__ void y_kernel(const float* __restrict__ W) {
    int k = blockIdx.x;
    int t = threadIdx.x;   // 128 threads, 4 cols each
    if (k >= KLAT) {
        #pragma unroll
        for (int i = 0; i < 4; i++) {
            g_Yhi[(size_t)k * DIM + t * 4 + i] = __float2half(0.f);
            g_Ylo[(size_t)k * DIM + t * 4 + i] = __float2half(0.f);
        }
        if (t == 0) g_ynorm[k] = 0.0f;
        return;
    }
    __shared__ float phis[MRBF];
    __shared__ double red[128];
    if (t < MRBF) phis[t] = g_phi[k * MRBF + t];
    if (t + 128 < MRBF) phis[t + 128] = g_phi[k * MRBF + t + 128];
    __syncthreads();

    float4 acc = make_float4(0.f, 0.f, 0.f, 0.f);
    const float4* W4 = (const float4*)W;
    #pragma unroll 4
    for (int m = 0; m < MRBF; m++) {
        float p = phis[m];
        float4 w = W4[m * (DIM / 4) + t];
        acc.x += p * w.x; acc.y += p * w.y; acc.z += p * w.z; acc.w += p * w.w;
    }
    float a[4] = {acc.x, acc.y, acc.z, acc.w};
    #pragma unroll
    for (int i = 0; i < 4; i++) {
        __half h = __float2half_rn(a[i]);
        __half l = __float2half_rn(a[i] - __half2float(h));
        g_Yhi[(size_t)k * DIM + t * 4 + i] = h;
        g_Ylo[(size_t)k * DIM + t * 4 + i] = l;
    }
    double ss = (double)acc.x * acc.x + (double)acc.y * acc.y +
                (double)acc.z * acc.z + (double)acc.w * acc.w;
    red[t] = ss;
    __syncthreads();
    for (int o = 64; o > 0; o >>= 1) {
        if (t < o) red[t] += red[t + o];
        __syncthreads();
    }
    if (t == 0) g_ynorm[k] = (float)red[0];
}

__global__ void noop_kernel() {}

// ---------------------------------------------------------------------------
// Main fused kernel: S = t @ Y^T via mma.sync f16 3-pass split (HMMA).
// Pass order per n-tile: (Ahi*Bhi, Alo*Bhi, Ahi*Blo) -> Bhi loaded once.
// B staged via cp.async; A fp16-split conversion overlaps B fetch.
// ---------------------------------------------------------------------------
__global__ void __launch_bounds__(NTHREADS, 1)
gtm_mma_kernel(const float* __restrict__ t_in, const float* __restrict__ beta,
               float* __restrict__ out, long long out_off) {
    extern __shared__ char smem[];
    const uint32_t sbase = smem_u32(smem);
    const int tid  = threadIdx.x;
    const int lane = tid & 31;
    const int wid  = tid >> 5;
    const int wr   = wid >> 2;   // warp row (0..3): rows wr*32..wr*32+31
    const int wc   = wid & 3;    // warp col (0..3): cols wc*96..wc*96+95
    const long long n0 = (long long)blockIdx.x * TM;

    float* yns = (float*)(smem + OFF_YN);
    if (tid < KP) yns[tid] = g_ynorm[tid];

    const float b  = beta[0];
    const float bh = 0.5f * b;

    // acc[mt][j][c]: m-tile (16 rows), n8-tile j (0..11), frag reg c
    float acc[2][12][4];
    #pragma unroll
    for (int mt = 0; mt < 2; mt++)
        #pragma unroll
        for (int j = 0; j < 12; j++)
            #pragma unroll
            for (int c = 0; c < 4; c++) acc[mt][j][c] = 0.0f;

    // per-thread ldmatrix row offsets (pre-swizzle)
    uint32_t rA[2], rB[6];
    #pragma unroll
    for (int mt = 0; mt < 2; mt++)
        rA[mt] = (uint32_t)((wr * 32 + mt * 16 + (lane & 15)) * 128 + ((lane >> 4) << 4));
    #pragma unroll
    for (int j6 = 0; j6 < 6; j6++)
        rB[j6] = (uint32_t)((wc * 96 + j6 * 16 + (lane & 15)) * 128 + ((lane >> 4) << 4));

    const uint32_t ahi_b = sbase + OFF_AHI;
    const uint32_t alo_b = sbase + OFF_ALO;
    const uint32_t bhi_b = sbase + OFF_BHI;
    const uint32_t blo_b = sbase + OFF_BLO;

    // A staging role: one 16-float segment per thread
    const int arow = tid >> 2;
    const int aseg = tid & 3;
    const float* asrc = t_in + (n0 + arow) * (long long)DIM + aseg * 16;
    const uint32_t aoff = (uint32_t)(arow * 128 + aseg * 32);
    const uint4* Yhi4 = (const uint4*)g_Yhi;   // row stride 64 uint4
    const uint4* Ylo4 = (const uint4*)g_Ylo;

    // B staging addresses (6 x 16B per thread per chunk)
    uint32_t bdst[6];
    int bsrc_r[6], bsrc_u[6];
    #pragma unroll
    for (int s = 0; s < 6; s++) {
        int idx = tid + s * 512;
        int r = idx >> 3, u = idx & 7;
        bdst[s] = swz((uint32_t)(r * 128 + u * 16));
        bsrc_r[s] = r; bsrc_u[s] = u;
    }

    for (int ci = 0; ci < NCHUNK; ci++) {
        // ---- B staging via cp.async (issued first, flows during A convert) ----
        #pragma unroll
        for (int s = 0; s < 6; s++) {
            const uint4* srch = &Yhi4[bsrc_r[s] * 64 + ci * 8 + bsrc_u[s]];
            const uint4* srcl = &Ylo4[bsrc_r[s] * 64 + ci * 8 + bsrc_u[s]];
            cp_async16(bhi_b + bdst[s], srch);
            cp_async16(blo_b + bdst[s], srcl);
        }
        CP_COMMIT();

        // ---- stage A (t chunk) with fp16 split ----
        {
            __align__(16) __half hi[16], lo[16];
            #pragma unroll
            for (int q = 0; q < 4; q++) {
                float4 v = *(const float4*)(asrc + ci * DC + q * 4);
                float x[4] = {v.x, v.y, v.z, v.w};
                #pragma unroll
                for (int e = 0; e < 4; e++) {
                    __half h = __float2half_rn(x[e]);
                    hi[q * 4 + e] = h;
                    lo[q * 4 + e] = __float2half_rn(x[e] - __half2float(h));
                }
            }
            *(uint4*)(smem + OFF_AHI + swz(aoff))      = ((uint4*)hi)[0];
            *(uint4*)(smem + OFF_AHI + swz(aoff + 16)) = ((uint4*)hi)[1];
            *(uint4*)(smem + OFF_ALO + swz(aoff))      = ((uint4*)lo)[0];
            *(uint4*)(smem + OFF_ALO + swz(aoff + 16)) = ((uint4*)lo)[1];
        }
        CP_WAIT0();
        __syncthreads();

        #pragma unroll
        for (int ks = 0; ks < 4; ks++) {
            const uint32_t ko = (uint32_t)(ks * 32);
            uint32_t ah[2][4], al[2][4];
            ldsm_x4(ah[0], ahi_b + swz(rA[0] + ko));
            ldsm_x4(ah[1], ahi_b + swz(rA[1] + ko));
            ldsm_x4(al[0], alo_b + swz(rA[0] + ko));
            ldsm_x4(al[1], alo_b + swz(rA[1] + ko));
            #pragma unroll
            for (int j6 = 0; j6 < 6; j6++) {
                uint32_t bf[4];
                ldsm_x4(bf, bhi_b + swz(rB[j6] + ko));
                #pragma unroll
                for (int mt = 0; mt < 2; mt++) {
                    mma16816(acc[mt][2 * j6 + 0], ah[mt], bf[0], bf[2]);
                    mma16816(acc[mt][2 * j6 + 1], ah[mt], bf[1], bf[3]);
                    mma16816(acc[mt][2 * j6 + 0], al[mt], bf[0], bf[2]);
                    mma16816(acc[mt][2 * j6 + 1], al[mt], bf[1], bf[3]);
                }
                ldsm_x4(bf, blo_b + swz(rB[j6] + ko));
                #pragma unroll
                for (int mt = 0; mt < 2; mt++) {
                    mma16816(acc[mt][2 * j6 + 0], ah[mt], bf[0], bf[2]);
                    mma16816(acc[mt][2 * j6 + 1], ah[mt], bf[1], bf[3]);
                }
            }
        }
        __syncthreads();
    }

    // ------------------------- epilogue -------------------------
    float* stage = (float*)(smem + OFF_STAGE);
    float* redm  = (float*)(smem + OFF_REDM);
    float* reds  = (float*)(smem + OFF_REDS);

    const int colb = wc * 96 + (lane & 3) * 2;

    // E = b*dot - bh*ynorm[col], mask col >= KLAT
    #pragma unroll
    for (int j = 0; j < 12; j++) {
        int c0 = colb + j * 8;
        float y0 = yns[c0], y1 = yns[c0 + 1];
        bool v0 = (c0 < KLAT), v1 = (c0 + 1 < KLAT);
        #pragma unroll
        for (int mt = 0; mt < 2; mt++) {
            #pragma unroll
            for (int h = 0; h < 2; h++) {
                float e0 = b * acc[mt][j][2 * h]     - bh * y0;
                float e1 = b * acc[mt][j][2 * h + 1] - bh * y1;
                acc[mt][j][2 * h]     = v0 ? e0 : -1e30f;
                acc[mt][j][2 * h + 1] = v1 ? e1 : -1e30f;
            }
        }
    }

    // row max (per warp, 4-lane groups share a row)
    #pragma unroll
    for (int mt = 0; mt < 2; mt++)
        #pragma unroll
        for (int h = 0; h < 2; h++) {
            float m = -FLT_MAX;
            #pragma unroll
            for (int j = 0; j < 12; j++)
                m = fmaxf(m, fmaxf(acc[mt][j][2 * h], acc[mt][j][2 * h + 1]));
            m = fmaxf(m, __shfl_xor_sync(0xffffffffu, m, 1));
            m = fmaxf(m, __shfl_xor_sync(0xffffffffu, m, 2));
            if ((lane & 3) == 0) {
                int row = wr * 32 + mt * 16 + h * 8 + (lane >> 2);
                redm[wc * 128 + row] = m;
            }
        }
    __syncthreads();

    float M[2][2], S[2][2];
    #pragma unroll
    for (int mt = 0; mt < 2; mt++)
        #pragma unroll
        for (int h = 0; h < 2; h++) {
            int row = wr * 32 + mt * 16 + h * 8 + (lane >> 2);
            M[mt][h] = fmaxf(fmaxf(redm[row], redm[128 + row]),
                             fmaxf(redm[256 + row], redm[384 + row]));
        }

    // exp + row sum (acc becomes p)
    #pragma unroll
    for (int mt = 0; mt < 2; mt++)
        #pragma unroll
        for (int h = 0; h < 2; h++) {
            float s = 0.0f;
            #pragma unroll
            for (int j = 0; j < 12; j++) {
                float p0 = __expf(acc[mt][j][2 * h]     - M[mt][h]);
                float p1 = __expf(acc[mt][j][2 * h + 1] - M[mt][h]);
                acc[mt][j][2 * h] = p0; acc[mt][j][2 * h + 1] = p1;
                s += p0 + p1;
            }
            s += __shfl_xor_sync(0xffffffffu, s, 1);
            s += __shfl_xor_sync(0xffffffffu, s, 2);
            if ((lane & 3) == 0) {
                int row = wr * 32 + mt * 16 + h * 8 + (lane >> 2);
                reds[wc * 128 + row] = s;
            }
        }
    __syncthreads();

    #pragma unroll
    for (int mt = 0; mt < 2; mt++)
        #pragma unroll
        for (int h = 0; h < 2; h++) {
            int row = wr * 32 + mt * 16 + h * 8 + (lane >> 2);
            S[mt][h] = reds[row] + reds[128 + row] + reds[256 + row] + reds[384 + row];
        }

    // normalized responsibilities -> stage (for coalesced output)
    #pragma unroll
    for (int mt = 0; mt < 2; mt++)
        #pragma unroll
        for (int h = 0; h < 2; h++) {
            int row = wr * 32 + mt * 16 + h * 8 + (lane >> 2);
            float inv = 1.0f / S[mt][h];
            float* srow = stage + row * STAGE_STRIDE;
            #pragma unroll
            for (int j = 0; j < 12; j++) {
                int c0 = colb + j * 8;
                if (c0 < KLAT)     srow[c0]     = acc[mt][j][2 * h] * inv;
                if (c0 + 1 < KLAT) srow[c0 + 1] = acc[mt][j][2 * h + 1] * inv;
            }
        }
    __syncthreads();

    // deterministic ll partial (warp 0)
    if (tid < 32) {
        double a = 0.0;
        #pragma unroll
        for (int i = 0; i < 4; i++) {
            int r = lane + i * 32;
            double st = (double)reds[r] + (double)reds[128 + r] +
                        (double)reds[256 + r] + (double)reds[384 + r];
            a += log(st);
        }
        #pragma unroll
        for (int o = 16; o > 0; o >>= 1)
            a += __shfl_xor_sync(0xffffffffu, a, o);
        if (lane == 0) g_partial[blockIdx.x] = a;
    }

    // coalesced store of R.T rows
    #pragma unroll
    for (int i = 0; i < 8; i++) {
        int r = wid + i * 16;
        const float* srow = stage + r * STAGE_STRIDE;
        float* orow = out + out_off + (n0 + r) * (long long)KLAT;
        #pragma unroll
        for (int s = 0; s < 12; s++) {
            int k = s * 32 + lane;
            if (k < KLAT) orow[k] = srow[k];
        }
    }
}

// ---------------------------------------------------------------------------
// Final reduce: out[0] = -ll
// ---------------------------------------------------------------------------
__global__ void final_kernel(const float* __restrict__ beta,
                             float* __restrict__ out, int Nrows, int nblocks) {
    __shared__ double red[1024];
    int tid = threadIdx.x;
    double s = 0.0;
    for (int i = tid; i < nblocks; i += 1024) s += g_partial[i];
    red[tid] = s;
    __syncthreads();
    for (int o = 512; o > 0; o >>= 1) {
        if (tid < o) red[tid] += red[tid + o];
        __syncthreads();
    }
    if (tid == 0) {
        double b = (double)beta[0];
        double cst = 256.0 * log(b / (2.0 * M_PI)) - log(360.0);
        double ll = ((double)Nrows * cst + red[0]) / (double)Nrows;
        out[0] = (float)(-ll);
    }
}

// ---------------------------------------------------------------------------
extern "C" void kernel_launch(void* const* d_in, const int* in_sizes, int n_in,
                              void* d_out, int out_size) {
    const float* t    = (const float*)d_in[0];
    const float* W    = (const float*)d_in[1];
    const float* beta = (const float*)d_in[2];
    float* out = (float*)d_out;

    int N = in_sizes[0] / DIM;                                  // 131072
    long long off = (long long)out_size - (long long)N * KLAT;  // scalar slot first
    if (off < 0) off = 0;

    static int smem_set = 0;
    if (!smem_set) {
        cudaFuncSetAttribute(gtm_mma_kernel,
                             cudaFuncAttributeMaxDynamicSharedMemorySize, SMEM_TOTAL);
        smem_set = 1;
    }

    phi_kernel<<<(KLAT * MRBF + 255) / 256, 256>>>();
    y_kernel<<<KP, 128>>>(W);
    noop_kernel<<<1, 32>>>();
    int ntiles = N / TM;        // 1024
    gtm_mma_kernel<<<ntiles, NTHREADS, SMEM_TOTAL>>>(t, beta, out, off);
    final_kernel<<<1, 1024>>>(beta, out, N, ntiles);
}

// round 6
// speedup vs baseline: 2.5991x; 1.0415x over previous
#include <cuda_runtime.h>
#include <cuda_fp16.h>
#include <math.h>
#include <float.h>
#include <stdint.h>

// ---------------------------------------------------------------------------
// Problem constants
// ---------------------------------------------------------------------------
#define DIM    512
#define KLAT   360
#define KP     384          // padded K
#define MRBF   145
#define TM     64           // t-rows per CTA
#define DC     32           // D-chunk (halves) -> 64 B rows, SW64
#define NCHUNK (DIM / DC)   // 16
#define NTHREADS 256

// SMEM layout (bytes). Pipeline: A 2buf x 2half x 4KB, B 2buf x 2half x 24KB.
#define ABUF(buf, lo)  ((buf) * 8192 + (lo) * 4096)            // 0 .. 16384
#define BBUF(buf, lo)  (16384 + (buf) * 49152 + (lo) * 24576)  // .. 114688
#define SMEM_TOTAL 114688
// Epilogue overlays the pipeline region:
#define OFF_STAGE 0
#define STAGE_STRIDE 372            // floats; 372 mod 32 = 20 -> rows spread banks
#define OFF_REDM  95232             // 4*64 floats
#define OFF_REDS  96256             // 4*64 floats
#define OFF_YN    97280             // 384 floats -> ends 98816

// Scratch (device globals; no allocation allowed)
__device__ float  g_phi[KLAT * MRBF];
__device__ float  g_ynorm[KP];
__device__ __half g_Yhi[KP * DIM];
__device__ __half g_Ylo[KP * DIM];
__device__ double g_partial[4096];

// ---------------------------------------------------------------------------
// helpers
// ---------------------------------------------------------------------------
__device__ __forceinline__ uint32_t smem_u32(const void* p) {
    uint32_t a;
    asm("{ .reg .u64 t; cvta.to.shared.u64 t, %1; cvt.u32.u64 %0, t; }"
        : "=r"(a) : "l"(p));
    return a;
}
__device__ __forceinline__ uint32_t swz64(uint32_t off) {
    return off ^ ((off >> 3) & 0x30);
}
__device__ __forceinline__ void ldsm_x4(uint32_t* r, uint32_t addr) {
    asm volatile("ldmatrix.sync.aligned.m8n8.x4.shared.b16 {%0,%1,%2,%3}, [%4];"
                 : "=r"(r[0]), "=r"(r[1]), "=r"(r[2]), "=r"(r[3]) : "r"(addr));
}
__device__ __forceinline__ void mma16816(float* c, const uint32_t* a,
                                         uint32_t b0, uint32_t b1) {
    asm volatile("mma.sync.aligned.m16n8k16.row.col.f32.f16.f16.f32 "
                 "{%0,%1,%2,%3}, {%4,%5,%6,%7}, {%8,%9}, {%0,%1,%2,%3};"
                 : "+f"(c[0]), "+f"(c[1]), "+f"(c[2]), "+f"(c[3])
                 : "r"(a[0]), "r"(a[1]), "r"(a[2]), "r"(a[3]), "r"(b0), "r"(b1));
}
__device__ __forceinline__ void cp_async16(uint32_t dst, const void* src) {
    asm volatile("cp.async.cg.shared.global [%0], [%1], 16;"
                 :: "r"(dst), "l"(src) : "memory");
}
#define CP_COMMIT() asm volatile("cp.async.commit_group;" ::: "memory")
#define CP_WAIT0()  asm volatile("cp.async.wait_group 0;" ::: "memory")
#define CP_WAIT1()  asm volatile("cp.async.wait_group 1;" ::: "memory")

// ---------------------------------------------------------------------------
// phi[k][m] = exp(-3 * ||x_k - c_m||^2)
// ---------------------------------------------------------------------------
__global__ void phi_kernel() {
    int idx = blockIdx.x * blockDim.x + threadIdx.x;
    if (idx >= KLAT * MRBF) return;
    int k = idx / MRBF, m = idx % MRBF;
    float val;
    if (m == MRBF - 1) {
        val = 1.0f;
    } else {
        int ia = k / 18, ib = k % 18;
        double x0 = -1.0 + ia * (2.0 / 19.0);
        double x1 = -1.0 + ib * (2.0 / 17.0);
        int mi = m / 12, mj = m % 12;
        double step = (2.0 - 2.0 / 12.0) / 11.0;
        double c0 = -1.0 + 1.0 / 12.0 + mi * step;
        double c1 = -1.0 + 1.0 / 12.0 + mj * step;
        double d2 = (x0 - c0) * (x0 - c0) + (x1 - c1) * (x1 - c1);
        val = (float)exp(-3.0 * d2);
    }
    g_phi[idx] = val;
}

// ---------------------------------------------------------------------------
// Y = phi @ W ; emit fp16 hi/lo split + ynorm. Pad rows zero.
// ---------------------------------------------------------------------------
__global__ void y_kernel(const float* __restrict__ W) {
    int k = blockIdx.x;
    int t = threadIdx.x;   // 128 threads, 4 cols each
    if (k >= KLAT) {
        #pragma unroll
        for (int i = 0; i < 4; i++) {
            g_Yhi[(size_t)k * DIM + t * 4 + i] = __float2half(0.f);
            g_Ylo[(size_t)k * DIM + t * 4 + i] = __float2half(0.f);
        }
        if (t == 0) g_ynorm[k] = 0.0f;
        return;
    }
    __shared__ float phis[MRBF];
    __shared__ double red[128];
    if (t < MRBF) phis[t] = g_phi[k * MRBF + t];
    if (t + 128 < MRBF) phis[t + 128] = g_phi[k * MRBF + t + 128];
    __syncthreads();

    float4 acc = make_float4(0.f, 0.f, 0.f, 0.f);
    const float4* W4 = (const float4*)W;
    #pragma unroll 4
    for (int m = 0; m < MRBF; m++) {
        float p = phis[m];
        float4 w = W4[m * (DIM / 4) + t];
        acc.x += p * w.x; acc.y += p * w.y; acc.z += p * w.z; acc.w += p * w.w;
    }
    float a[4] = {acc.x, acc.y, acc.z, acc.w};
    #pragma unroll
    for (int i = 0; i < 4; i++) {
        __half h = __float2half_rn(a[i]);
        __half l = __float2half_rn(a[i] - __half2float(h));
        g_Yhi[(size_t)k * DIM + t * 4 + i] = h;
        g_Ylo[(size_t)k * DIM + t * 4 + i] = l;
    }
    double ss = (double)acc.x * acc.x + (double)acc.y * acc.y +
                (double)acc.z * acc.z + (double)acc.w * acc.w;
    red[t] = ss;
    __syncthreads();
    for (int o = 64; o > 0; o >>= 1) {
        if (t < o) red[t] += red[t + o];
        __syncthreads();
    }
    if (t == 0) g_ynorm[k] = (float)red[0];
}

__global__ void noop_kernel() {}

// ---------------------------------------------------------------------------
// Main fused kernel: 256 threads, TM=64, 2 CTAs/SM, double-buffered DC=32.
// B prefetched via cp.async one chunk ahead; A (t fp16-split) staged post-MMA.
// ---------------------------------------------------------------------------
__global__ void __launch_bounds__(NTHREADS, 2)
gtm_mma_kernel(const float* __restrict__ t_in, const float* __restrict__ beta,
               float* __restrict__ out, long long out_off) {
    extern __shared__ char smem[];
    const uint32_t sbase = smem_u32(smem);
    const int tid  = threadIdx.x;
    const int lane = tid & 31;
    const int wid  = tid >> 5;
    const int wr   = wid >> 2;   // 0..1: rows wr*32..+31
    const int wc   = wid & 3;    // 0..3: cols wc*96..+95
    const long long n0 = (long long)blockIdx.x * TM;

    const float b  = beta[0];
    const float bh = 0.5f * b;

    float acc[2][12][4];
    #pragma unroll
    for (int mt = 0; mt < 2; mt++)
        #pragma unroll
        for (int j = 0; j < 12; j++)
            #pragma unroll
            for (int c = 0; c < 4; c++) acc[mt][j][c] = 0.0f;

    // ldmatrix per-thread base offsets (pre-swizzle), 64B rows
    uint32_t rAb[2], rBb[6];
    #pragma unroll
    for (int mt = 0; mt < 2; mt++)
        rAb[mt] = (uint32_t)((wr * 32 + mt * 16 + (lane & 15)) * 64 + ((lane >> 4) << 4));
    #pragma unroll
    for (int j6 = 0; j6 < 6; j6++)
        rBb[j6] = (uint32_t)((wc * 96 + j6 * 16 + (lane & 15)) * 64 + ((lane >> 4) << 4));

    // staging roles
    const int arow = tid >> 2, au = tid & 3;                     // A: 1 granule/half
    const float* asrc0 = t_in + (n0 + arow) * (long long)DIM + au * 8;
    const uint32_t adst = swz64((uint32_t)(arow * 64 + au * 16));
    const int brow = tid >> 2, bu = tid & 3;                     // B: 6 granules/half
    const uint32_t bdst0 = swz64((uint32_t)(brow * 64 + bu * 16));
    const uint4* Yhi4 = (const uint4*)g_Yhi;    // 64 uint4 per row
    const uint4* Ylo4 = (const uint4*)g_Ylo;

    // ---- staging lambdas (macros by hand) ----
    #define STAGE_B(ci, buf) do {                                              \
        uint32_t _dh = sbase + BBUF(buf, 0) + bdst0;                           \
        uint32_t _dl = sbase + BBUF(buf, 1) + bdst0;                           \
        const uint4* _sh = Yhi4 + (size_t)brow * 64 + (ci) * 4 + bu;           \
        const uint4* _sl = Ylo4 + (size_t)brow * 64 + (ci) * 4 + bu;           \
        _Pragma("unroll")                                                      \
        for (int _s = 0; _s < 6; _s++) {                                       \
            cp_async16(_dh + _s * 4096, _sh + (size_t)_s * 4096);              \
            cp_async16(_dl + _s * 4096, _sl + (size_t)_s * 4096);              \
        }                                                                      \
    } while (0)

    #define STAGE_A(ci, buf) do {                                              \
        float4 _v0 = *(const float4*)(asrc0 + (ci) * DC);                      \
        float4 _v1 = *(const float4*)(asrc0 + (ci) * DC + 4);                  \
        float _x[8] = {_v0.x,_v0.y,_v0.z,_v0.w,_v1.x,_v1.y,_v1.z,_v1.w};       \
        __align__(16) __half _hi[8], _lo[8];                                   \
        _Pragma("unroll")                                                      \
        for (int _e = 0; _e < 8; _e++) {                                       \
            __half _h = __float2half_rn(_x[_e]);                               \
            _hi[_e] = _h;                                                      \
            _lo[_e] = __float2half_rn(_x[_e] - __half2float(_h));              \
        }                                                                      \
        *(uint4*)(smem + ABUF(buf, 0) + adst) = *(uint4*)_hi;                  \
        *(uint4*)(smem + ABUF(buf, 1) + adst) = *(uint4*)_lo;                  \
    } while (0)

    // prologue
    STAGE_B(0, 0); CP_COMMIT();
    STAGE_A(0, 0);

    for (int ci = 0; ci < NCHUNK; ci++) {
        const int buf = ci & 1;
        if (ci + 1 < NCHUNK) { STAGE_B(ci + 1, buf ^ 1); CP_COMMIT(); }
        if (ci + 1 < NCHUNK) CP_WAIT1(); else CP_WAIT0();
        __syncthreads();

        const uint32_t ahi = sbase + ABUF(buf, 0);
        const uint32_t alo = sbase + ABUF(buf, 1);
        const uint32_t bhi = sbase + BBUF(buf, 0);
        const uint32_t blo = sbase + BBUF(buf, 1);

        #pragma unroll
        for (int ks = 0; ks < 2; ks++) {
            const uint32_t ko = (uint32_t)(ks * 32);
            uint32_t ah[2][4], al[2][4];
            ldsm_x4(ah[0], ahi + swz64(rAb[0] + ko));
            ldsm_x4(ah[1], ahi + swz64(rAb[1] + ko));
            ldsm_x4(al[0], alo + swz64(rAb[0] + ko));
            ldsm_x4(al[1], alo + swz64(rAb[1] + ko));
            #pragma unroll
            for (int j6 = 0; j6 < 6; j6++) {
                uint32_t bf[4];
                ldsm_x4(bf, bhi + swz64(rBb[j6] + ko));
                #pragma unroll
                for (int mt = 0; mt < 2; mt++) {
                    mma16816(acc[mt][2 * j6 + 0], ah[mt], bf[0], bf[2]);
                    mma16816(acc[mt][2 * j6 + 1], ah[mt], bf[1], bf[3]);
                    mma16816(acc[mt][2 * j6 + 0], al[mt], bf[0], bf[2]);
                    mma16816(acc[mt][2 * j6 + 1], al[mt], bf[1], bf[3]);
                }
                ldsm_x4(bf, blo + swz64(rBb[j6] + ko));
                #pragma unroll
                for (int mt = 0; mt < 2; mt++) {
                    mma16816(acc[mt][2 * j6 + 0], ah[mt], bf[0], bf[2]);
                    mma16816(acc[mt][2 * j6 + 1], ah[mt], bf[1], bf[3]);
                }
            }
        }
        if (ci + 1 < NCHUNK) STAGE_A(ci + 1, buf ^ 1);
        __syncthreads();
    }

    // ------------------------- epilogue -------------------------
    float* stage = (float*)(smem + OFF_STAGE);
    float* redm  = (float*)(smem + OFF_REDM);
    float* reds  = (float*)(smem + OFF_REDS);
    float* yns   = (float*)(smem + OFF_YN);

    yns[tid] = g_ynorm[tid];
    if (tid + 256 < KP) yns[tid + 256] = g_ynorm[tid + 256];
    __syncthreads();

    const int colb = wc * 96 + (lane & 3) * 2;

    // E = b*dot - bh*ynorm[col], mask col >= KLAT
    #pragma unroll
    for (int j = 0; j < 12; j++) {
        int c0 = colb + j * 8;
        float y0 = yns[c0], y1 = yns[c0 + 1];
        bool v0 = (c0 < KLAT), v1 = (c0 + 1 < KLAT);
        #pragma unroll
        for (int mt = 0; mt < 2; mt++)
            #pragma unroll
            for (int h = 0; h < 2; h++) {
                float e0 = b * acc[mt][j][2 * h]     - bh * y0;
                float e1 = b * acc[mt][j][2 * h + 1] - bh * y1;
                acc[mt][j][2 * h]     = v0 ? e0 : -1e30f;
                acc[mt][j][2 * h + 1] = v1 ? e1 : -1e30f;
            }
    }

    // row max
    #pragma unroll
    for (int mt = 0; mt < 2; mt++)
        #pragma unroll
        for (int h = 0; h < 2; h++) {
            float m = -FLT_MAX;
            #pragma unroll
            for (int j = 0; j < 12; j++)
                m = fmaxf(m, fmaxf(acc[mt][j][2 * h], acc[mt][j][2 * h + 1]));
            m = fmaxf(m, __shfl_xor_sync(0xffffffffu, m, 1));
            m = fmaxf(m, __shfl_xor_sync(0xffffffffu, m, 2));
            if ((lane & 3) == 0) {
                int row = wr * 32 + mt * 16 + h * 8 + (lane >> 2);
                redm[wc * 64 + row] = m;
            }
        }
    __syncthreads();

    float M[2][2], S[2][2];
    #pragma unroll
    for (int mt = 0; mt < 2; mt++)
        #pragma unroll
        for (int h = 0; h < 2; h++) {
            int row = wr * 32 + mt * 16 + h * 8 + (lane >> 2);
            M[mt][h] = fmaxf(fmaxf(redm[row], redm[64 + row]),
                             fmaxf(redm[128 + row], redm[192 + row]));
        }

    // exp + row sum
    #pragma unroll
    for (int mt = 0; mt < 2; mt++)
        #pragma unroll
        for (int h = 0; h < 2; h++) {
            float s = 0.0f;
            #pragma unroll
            for (int j = 0; j < 12; j++) {
                float p0 = __expf(acc[mt][j][2 * h]     - M[mt][h]);
                float p1 = __expf(acc[mt][j][2 * h + 1] - M[mt][h]);
                acc[mt][j][2 * h] = p0; acc[mt][j][2 * h + 1] = p1;
                s += p0 + p1;
            }
            s += __shfl_xor_sync(0xffffffffu, s, 1);
            s += __shfl_xor_sync(0xffffffffu, s, 2);
            if ((lane & 3) == 0) {
                int row = wr * 32 + mt * 16 + h * 8 + (lane >> 2);
                reds[wc * 64 + row] = s;
            }
        }
    __syncthreads();

    #pragma unroll
    for (int mt = 0; mt < 2; mt++)
        #pragma unroll
        for (int h = 0; h < 2; h++) {
            int row = wr * 32 + mt * 16 + h * 8 + (lane >> 2);
            S[mt][h] = reds[row] + reds[64 + row] + reds[128 + row] + reds[192 + row];
        }

    // normalized responsibilities -> stage
    #pragma unroll
    for (int mt = 0; mt < 2; mt++)
        #pragma unroll
        for (int h = 0; h < 2; h++) {
            int row = wr * 32 + mt * 16 + h * 8 + (lane >> 2);
            float inv = 1.0f / S[mt][h];
            float* srow = stage + row * STAGE_STRIDE;
            #pragma unroll
            for (int j = 0; j < 12; j++) {
                int c0 = colb + j * 8;
                if (c0 < KLAT)     srow[c0]     = acc[mt][j][2 * h] * inv;
                if (c0 + 1 < KLAT) srow[c0 + 1] = acc[mt][j][2 * h + 1] * inv;
            }
        }
    __syncthreads();

    // deterministic ll partial (warp 0): 64 rows, 2 per lane
    if (tid < 32) {
        double a = 0.0;
        #pragma unroll
        for (int i = 0; i < 2; i++) {
            int r = lane + i * 32;
            double st = (double)reds[r] + (double)reds[64 + r] +
                        (double)reds[128 + r] + (double)reds[192 + r];
            a += log(st);
        }
        #pragma unroll
        for (int o = 16; o > 0; o >>= 1)
            a += __shfl_xor_sync(0xffffffffu, a, o);
        if (lane == 0) g_partial[blockIdx.x] = a;
    }

    // coalesced store of R.T rows
    #pragma unroll
    for (int i = 0; i < 8; i++) {
        int r = wid + i * 8;
        const float* srow = stage + r * STAGE_STRIDE;
        float* orow = out + out_off + (n0 + r) * (long long)KLAT;
        #pragma unroll
        for (int s = 0; s < 12; s++) {
            int k = s * 32 + lane;
            if (k < KLAT) orow[k] = srow[k];
        }
    }
    #undef STAGE_A
    #undef STAGE_B
}

// ---------------------------------------------------------------------------
// Final reduce: out[0] = -ll
// ---------------------------------------------------------------------------
__global__ void final_kernel(const float* __restrict__ beta,
                             float* __restrict__ out, int Nrows, int nblocks) {
    __shared__ double red[1024];
    int tid = threadIdx.x;
    double s = 0.0;
    for (int i = tid; i < nblocks; i += 1024) s += g_partial[i];
    red[tid] = s;
    __syncthreads();
    for (int o = 512; o > 0; o >>= 1) {
        if (tid < o) red[tid] += red[tid + o];
        __syncthreads();
    }
    if (tid == 0) {
        double b = (double)beta[0];
        double cst = 256.0 * log(b / (2.0 * M_PI)) - log(360.0);
        double ll = ((double)Nrows * cst + red[0]) / (double)Nrows;
        out[0] = (float)(-ll);
    }
}

// ---------------------------------------------------------------------------
extern "C" void kernel_launch(void* const* d_in, const int* in_sizes, int n_in,
                              void* d_out, int out_size) {
    const float* t    = (const float*)d_in[0];
    const float* W    = (const float*)d_in[1];
    const float* beta = (const float*)d_in[2];
    float* out = (float*)d_out;

    int N = in_sizes[0] / DIM;                                  // 131072
    long long off = (long long)out_size - (long long)N * KLAT;  // scalar slot first
    if (off < 0) off = 0;

    static int smem_set = 0;
    if (!smem_set) {
        cudaFuncSetAttribute(gtm_mma_kernel,
                             cudaFuncAttributeMaxDynamicSharedMemorySize, SMEM_TOTAL);
        smem_set = 1;
    }

    phi_kernel<<<(KLAT * MRBF + 255) / 256, 256>>>();
    y_kernel<<<KP, 128>>>(W);
    noop_kernel<<<1, 32>>>();
    int ntiles = N / TM;        // 2048
    gtm_mma_kernel<<<ntiles, NTHREADS, SMEM_TOTAL>>>(t, beta, out, off);
    final_kernel<<<1, 1024>>>(beta, out, N, ntiles);
}

// round 8
// speedup vs baseline: 2.7352x; 1.0524x over previous
#include <cuda_runtime.h>
#include <cuda_fp16.h>
#include <math.h>
#include <float.h>
#include <stdint.h>

// ---------------------------------------------------------------------------
// Problem constants
// ---------------------------------------------------------------------------
#define DIM    512
#define KLAT   360
#define KP     384          // padded K
#define MRBF   145
#define TM     64           // t-rows per CTA
#define DC     32           // D-chunk (halves) -> 64 B rows, SW64
#define NCHUNK (DIM / DC)   // 16
#define NTHREADS 256

// SMEM layout (bytes). Pipeline: A 2buf x 2half x 4KB, B 2buf x 2half x 24KB.
#define ABUF(buf, lo)  ((buf) * 8192 + (lo) * 4096)            // 0 .. 16384
#define BBUF(buf, lo)  (16384 + (buf) * 49152 + (lo) * 24576)  // .. 114688
#define SMEM_TOTAL 114688
// Epilogue overlays the pipeline region:
#define OFF_STAGE 0
#define STAGE_STRIDE 372            // floats
#define OFF_REDM  95232             // 4*64 floats
#define OFF_REDS  96256             // 4*64 floats
#define OFF_YN    97280             // 384 floats -> ends 98816

// Scratch (device globals; no allocation allowed)
__device__ float  g_phi[KLAT * MRBF];
__device__ float  g_ynorm[KP];
__device__ __half g_Yhi[KP * DIM];
__device__ __half g_Ylo[KP * DIM];
__device__ double g_partial[4096];

// ---------------------------------------------------------------------------
// helpers
// ---------------------------------------------------------------------------
__device__ __forceinline__ uint32_t smem_u32(const void* p) {
    uint32_t a;
    asm("{ .reg .u64 t; cvta.to.shared.u64 t, %1; cvt.u32.u64 %0, t; }"
        : "=r"(a) : "l"(p));
    return a;
}
__device__ __forceinline__ uint32_t swz64(uint32_t off) {
    return off ^ ((off >> 3) & 0x30);
}
__device__ __forceinline__ void ldsm_x4(uint32_t* r, uint32_t addr) {
    asm volatile("ldmatrix.sync.aligned.m8n8.x4.shared.b16 {%0,%1,%2,%3}, [%4];"
                 : "=r"(r[0]), "=r"(r[1]), "=r"(r[2]), "=r"(r[3]) : "r"(addr));
}
__device__ __forceinline__ void mma16816(float* c, const uint32_t* a,
                                         uint32_t b0, uint32_t b1) {
    asm volatile("mma.sync.aligned.m16n8k16.row.col.f32.f16.f16.f32 "
                 "{%0,%1,%2,%3}, {%4,%5,%6,%7}, {%8,%9}, {%0,%1,%2,%3};"
                 : "+f"(c[0]), "+f"(c[1]), "+f"(c[2]), "+f"(c[3])
                 : "r"(a[0]), "r"(a[1]), "r"(a[2]), "r"(a[3]), "r"(b0), "r"(b1));
}
__device__ __forceinline__ void cp_async16(uint32_t dst, const void* src) {
    asm volatile("cp.async.cg.shared.global [%0], [%1], 16;"
                 :: "r"(dst), "l"(src) : "memory");
}
#define CP_COMMIT() asm volatile("cp.async.commit_group;" ::: "memory")
#define CP_WAIT0()  asm volatile("cp.async.wait_group 0;" ::: "memory")

// ---------------------------------------------------------------------------
// phi[k][m] = exp(-3 * ||x_k - c_m||^2)
// ---------------------------------------------------------------------------
__global__ void phi_kernel() {
    int idx = blockIdx.x * blockDim.x + threadIdx.x;
    if (idx >= KLAT * MRBF) return;
    int k = idx / MRBF, m = idx % MRBF;
    float val;
    if (m == MRBF - 1) {
        val = 1.0f;
    } else {
        int ia = k / 18, ib = k % 18;
        double x0 = -1.0 + ia * (2.0 / 19.0);
        double x1 = -1.0 + ib * (2.0 / 17.0);
        int mi = m / 12, mj = m % 12;
        double step = (2.0 - 2.0 / 12.0) / 11.0;
        double c0 = -1.0 + 1.0 / 12.0 + mi * step;
        double c1 = -1.0 + 1.0 / 12.0 + mj * step;
        double d2 = (x0 - c0) * (x0 - c0) + (x1 - c1) * (x1 - c1);
        val = (float)exp(-3.0 * d2);
    }
    g_phi[idx] = val;
}

// ---------------------------------------------------------------------------
// Y = phi @ W ; emit fp16 hi/lo split + ynorm. Pad rows zero.
// ---------------------------------------------------------------------------
__global__ void y_kernel(const float* __restrict__ W) {
    int k = blockIdx.x;
    int t = threadIdx.x;   // 128 threads, 4 cols each
    if (k >= KLAT) {
        #pragma unroll
        for (int i = 0; i < 4; i++) {
            g_Yhi[(size_t)k * DIM + t * 4 + i] = __float2half(0.f);
            g_Ylo[(size_t)k * DIM + t * 4 + i] = __float2half(0.f);
        }
        if (t == 0) g_ynorm[k] = 0.0f;
        return;
    }
    __shared__ float phis[MRBF];
    __shared__ double red[128];
    if (t < MRBF) phis[t] = g_phi[k * MRBF + t];
    if (t + 128 < MRBF) phis[t + 128] = g_phi[k * MRBF + t + 128];
    __syncthreads();

    float4 acc = make_float4(0.f, 0.f, 0.f, 0.f);
    const float4* W4 = (const float4*)W;
    #pragma unroll 4
    for (int m = 0; m < MRBF; m++) {
        float p = phis[m];
        float4 w = W4[m * (DIM / 4) + t];
        acc.x += p * w.x; acc.y += p * w.y; acc.z += p * w.z; acc.w += p * w.w;
    }
    float a[4] = {acc.x, acc.y, acc.z, acc.w};
    #pragma unroll
    for (int i = 0; i < 4; i++) {
        __half h = __float2half_rn(a[i]);
        __half l = __float2half_rn(a[i] - __half2float(h));
        g_Yhi[(size_t)k * DIM + t * 4 + i] = h;
        g_Ylo[(size_t)k * DIM + t * 4 + i] = l;
    }
    double ss = (double)acc.x * acc.x + (double)acc.y * acc.y +
                (double)acc.z * acc.z + (double)acc.w * acc.w;
    red[t] = ss;
    __syncthreads();
    for (int o = 64; o > 0; o >>= 1) {
        if (t < o) red[t] += red[t + o];
        __syncthreads();
    }
    if (t == 0) g_ynorm[k] = (float)red[0];
}

__global__ void noop_kernel() {}

// ---------------------------------------------------------------------------
// Main fused kernel: 256 threads, TM=64, 2 CTAs/SM, double-buffered DC=32.
// Pass-major MMA order per j6 (acc RAW reuse distance 4); one sync per chunk.
// Swizzle computed inline on the full offset (base + ko) — NOT hoistable.
// ---------------------------------------------------------------------------
__global__ void __launch_bounds__(NTHREADS, 2)
gtm_mma_kernel(const float* __restrict__ t_in, const float* __restrict__ beta,
               float* __restrict__ out, long long out_off) {
    extern __shared__ char smem[];
    const uint32_t sbase = smem_u32(smem);
    const int tid  = threadIdx.x;
    const int lane = tid & 31;
    const int wid  = tid >> 5;
    const int wr   = wid >> 2;   // 0..1: rows wr*32..+31
    const int wc   = wid & 3;    // 0..3: cols wc*96..+95
    const long long n0 = (long long)blockIdx.x * TM;

    const float b  = beta[0];
    const float bh = 0.5f * b;

    float acc[2][12][4];
    #pragma unroll
    for (int mt = 0; mt < 2; mt++)
        #pragma unroll
        for (int j = 0; j < 12; j++)
            #pragma unroll
            for (int c = 0; c < 4; c++) acc[mt][j][c] = 0.0f;

    // ldmatrix per-thread base offsets (UNswizzled; swizzle applied per access)
    uint32_t rAb[2], rBb[6];
    #pragma unroll
    for (int mt = 0; mt < 2; mt++)
        rAb[mt] = (uint32_t)((wr * 32 + mt * 16 + (lane & 15)) * 64 + ((lane >> 4) << 4));
    #pragma unroll
    for (int j6 = 0; j6 < 6; j6++)
        rBb[j6] = (uint32_t)((wc * 96 + j6 * 16 + (lane & 15)) * 64 + ((lane >> 4) << 4));

    // staging roles
    const int arow = tid >> 2, au = tid & 3;                     // A: 1 granule/half
    const float* asrc0 = t_in + (n0 + arow) * (long long)DIM + au * 8;
    const uint32_t adst = swz64((uint32_t)(arow * 64 + au * 16));
    const int brow = tid >> 2, bu = tid & 3;                     // B: 6 granules/half
    const uint32_t bdst0 = swz64((uint32_t)(brow * 64 + bu * 16));
    const uint4* bsrc_h = (const uint4*)g_Yhi + (size_t)brow * 64 + bu;
    const uint4* bsrc_l = (const uint4*)g_Ylo + (size_t)brow * 64 + bu;

    #define STAGE_B(ci, buf) do {                                              \
        uint32_t _dh = sbase + BBUF(buf, 0) + bdst0;                           \
        uint32_t _dl = sbase + BBUF(buf, 1) + bdst0;                           \
        const uint4* _sh = bsrc_h + (ci) * 4;                                  \
        const uint4* _sl = bsrc_l + (ci) * 4;                                  \
        _Pragma("unroll")                                                      \
        for (int _s = 0; _s < 6; _s++) {                                       \
            cp_async16(_dh + _s * 4096, _sh + (size_t)_s * 4096);              \
            cp_async16(_dl + _s * 4096, _sl + (size_t)_s * 4096);              \
        }                                                                      \
    } while (0)

    #define STAGE_A(ci, buf) do {                                              \
        float4 _v0 = *(const float4*)(asrc0 + (ci) * DC);                      \
        float4 _v1 = *(const float4*)(asrc0 + (ci) * DC + 4);                  \
        float _x[8] = {_v0.x,_v0.y,_v0.z,_v0.w,_v1.x,_v1.y,_v1.z,_v1.w};       \
        __align__(16) __half _hi[8], _lo[8];                                   \
        _Pragma("unroll")                                                      \
        for (int _e = 0; _e < 8; _e++) {                                       \
            __half _h = __float2half_rn(_x[_e]);                               \
            _hi[_e] = _h;                                                      \
            _lo[_e] = __float2half_rn(_x[_e] - __half2float(_h));              \
        }                                                                      \
        *(uint4*)(smem + ABUF(buf, 0) + adst) = *(uint4*)_hi;                  \
        *(uint4*)(smem + ABUF(buf, 1) + adst) = *(uint4*)_lo;                  \
    } while (0)

    // prologue: stage chunk 0
    STAGE_B(0, 0); CP_COMMIT();
    STAGE_A(0, 0);

    for (int ci = 0; ci < NCHUNK; ci++) {
        const int buf = ci & 1;
        CP_WAIT0();
        __syncthreads();   // B(ci) visible to all; all done reading buf^1

        if (ci + 1 < NCHUNK) { STAGE_B(ci + 1, buf ^ 1); CP_COMMIT(); }

        const uint32_t ahi = sbase + ABUF(buf, 0);
        const uint32_t alo = sbase + ABUF(buf, 1);
        const uint32_t bhi = sbase + BBUF(buf, 0);
        const uint32_t blo = sbase + BBUF(buf, 1);

        #pragma unroll
        for (int ks = 0; ks < 2; ks++) {
            const uint32_t ko = (uint32_t)(ks * 32);
            uint32_t ah[2][4], al[2][4];
            ldsm_x4(ah[0], ahi + swz64(rAb[0] + ko));
            ldsm_x4(ah[1], ahi + swz64(rAb[1] + ko));
            ldsm_x4(al[0], alo + swz64(rAb[0] + ko));
            ldsm_x4(al[1], alo + swz64(rAb[1] + ko));
            #pragma unroll
            for (int j6 = 0; j6 < 6; j6++) {
                uint32_t bhf[4], blf[4];
                ldsm_x4(bhf, bhi + swz64(rBb[j6] + ko));
                ldsm_x4(blf, blo + swz64(rBb[j6] + ko));
                // pass 1: Ahi*Bhi (4 independent targets)
                mma16816(acc[0][2 * j6 + 0], ah[0], bhf[0], bhf[2]);
                mma16816(acc[0][2 * j6 + 1], ah[0], bhf[1], bhf[3]);
                mma16816(acc[1][2 * j6 + 0], ah[1], bhf[0], bhf[2]);
                mma16816(acc[1][2 * j6 + 1], ah[1], bhf[1], bhf[3]);
                // pass 2: Alo*Bhi
                mma16816(acc[0][2 * j6 + 0], al[0], bhf[0], bhf[2]);
                mma16816(acc[0][2 * j6 + 1], al[0], bhf[1], bhf[3]);
                mma16816(acc[1][2 * j6 + 0], al[1], bhf[0], bhf[2]);
                mma16816(acc[1][2 * j6 + 1], al[1], bhf[1], bhf[3]);
                // pass 3: Ahi*Blo
                mma16816(acc[0][2 * j6 + 0], ah[0], blf[0], blf[2]);
                mma16816(acc[0][2 * j6 + 1], ah[0], blf[1], blf[3]);
                mma16816(acc[1][2 * j6 + 0], ah[1], blf[0], blf[2]);
                mma16816(acc[1][2 * j6 + 1], ah[1], blf[1], blf[3]);
            }
        }
        if (ci + 1 < NCHUNK) STAGE_A(ci + 1, buf ^ 1);
    }
    __syncthreads();

    // ------------------------- epilogue -------------------------
    float* stage = (float*)(smem + OFF_STAGE);
    float* redm  = (float*)(smem + OFF_REDM);
    float* reds  = (float*)(smem + OFF_REDS);
    float* yns   = (float*)(smem + OFF_YN);

    yns[tid] = g_ynorm[tid];
    if (tid + 256 < KP) yns[tid + 256] = g_ynorm[tid + 256];
    __syncthreads();

    const int colb = wc * 96 + (lane & 3) * 2;

    // E = b*dot - bh*ynorm[col], mask col >= KLAT
    #pragma unroll
    for (int j = 0; j < 12; j++) {
        int c0 = colb + j * 8;
        float y0 = yns[c0], y1 = yns[c0 + 1];
        bool v0 = (c0 < KLAT), v1 = (c0 + 1 < KLAT);
        #pragma unroll
        for (int mt = 0; mt < 2; mt++)
            #pragma unroll
            for (int h = 0; h < 2; h++) {
                float e0 = b * acc[mt][j][2 * h]     - bh * y0;
                float e1 = b * acc[mt][j][2 * h + 1] - bh * y1;
                acc[mt][j][2 * h]     = v0 ? e0 : -1e30f;
                acc[mt][j][2 * h + 1] = v1 ? e1 : -1e30f;
            }
    }

    // row max
    #pragma unroll
    for (int mt = 0; mt < 2; mt++)
        #pragma unroll
        for (int h = 0; h < 2; h++) {
            float m = -FLT_MAX;
            #pragma unroll
            for (int j = 0; j < 12; j++)
                m = fmaxf(m, fmaxf(acc[mt][j][2 * h], acc[mt][j][2 * h + 1]));
            m = fmaxf(m, __shfl_xor_sync(0xffffffffu, m, 1));
            m = fmaxf(m, __shfl_xor_sync(0xffffffffu, m, 2));
            if ((lane & 3) == 0) {
                int row = wr * 32 + mt * 16 + h * 8 + (lane >> 2);
                redm[wc * 64 + row] = m;
            }
        }
    __syncthreads();

    float M[2][2], S[2][2];
    #pragma unroll
    for (int mt = 0; mt < 2; mt++)
        #pragma unroll
        for (int h = 0; h < 2; h++) {
            int row = wr * 32 + mt * 16 + h * 8 + (lane >> 2);
            M[mt][h] = fmaxf(fmaxf(redm[row], redm[64 + row]),
                             fmaxf(redm[128 + row], redm[192 + row]));
        }

    // exp + row sum
    #pragma unroll
    for (int mt = 0; mt < 2; mt++)
        #pragma unroll
        for (int h = 0; h < 2; h++) {
            float s = 0.0f;
            #pragma unroll
            for (int j = 0; j < 12; j++) {
                float p0 = __expf(acc[mt][j][2 * h]     - M[mt][h]);
                float p1 = __expf(acc[mt][j][2 * h + 1] - M[mt][h]);
                acc[mt][j][2 * h] = p0; acc[mt][j][2 * h + 1] = p1;
                s += p0 + p1;
            }
            s += __shfl_xor_sync(0xffffffffu, s, 1);
            s += __shfl_xor_sync(0xffffffffu, s, 2);
            if ((lane & 3) == 0) {
                int row = wr * 32 + mt * 16 + h * 8 + (lane >> 2);
                reds[wc * 64 + row] = s;
            }
        }
    __syncthreads();

    #pragma unroll
    for (int mt = 0; mt < 2; mt++)
        #pragma unroll
        for (int h = 0; h < 2; h++) {
            int row = wr * 32 + mt * 16 + h * 8 + (lane >> 2);
            S[mt][h] = reds[row] + reds[64 + row] + reds[128 + row] + reds[192 + row];
        }

    // normalized responsibilities -> stage
    #pragma unroll
    for (int mt = 0; mt < 2; mt++)
        #pragma unroll
        for (int h = 0; h < 2; h++) {
            int row = wr * 32 + mt * 16 + h * 8 + (lane >> 2);
            float inv = 1.0f / S[mt][h];
            float* srow = stage + row * STAGE_STRIDE;
            #pragma unroll
            for (int j = 0; j < 12; j++) {
                int c0 = colb + j * 8;
                if (c0 < KLAT)     srow[c0]     = acc[mt][j][2 * h] * inv;
                if (c0 + 1 < KLAT) srow[c0 + 1] = acc[mt][j][2 * h + 1] * inv;
            }
        }
    __syncthreads();

    // deterministic ll partial (warp 0): 64 rows, 2 per lane
    if (tid < 32) {
        double a = 0.0;
        #pragma unroll
        for (int i = 0; i < 2; i++) {
            int r = lane + i * 32;
            double st = (double)reds[r] + (double)reds[64 + r] +
                        (double)reds[128 + r] + (double)reds[192 + r];
            a += log(st);
        }
        #pragma unroll
        for (int o = 16; o > 0; o >>= 1)
            a += __shfl_xor_sync(0xffffffffu, a, o);
        if (lane == 0) g_partial[blockIdx.x] = a;
    }

    // coalesced store of R.T rows
    #pragma unroll
    for (int i = 0; i < 8; i++) {
        int r = wid + i * 8;
        const float* srow = stage + r * STAGE_STRIDE;
        float* orow = out + out_off + (n0 + r) * (long long)KLAT;
        #pragma unroll
        for (int s = 0; s < 12; s++) {
            int k = s * 32 + lane;
            if (k < KLAT) orow[k] = srow[k];
        }
    }
    #undef STAGE_A
    #undef STAGE_B
}

// ---------------------------------------------------------------------------
// Final reduce: out[0] = -ll
// ---------------------------------------------------------------------------
__global__ void final_kernel(const float* __restrict__ beta,
                             float* __restrict__ out, int Nrows, int nblocks) {
    __shared__ double red[1024];
    int tid = threadIdx.x;
    double s = 0.0;
    for (int i = tid; i < nblocks; i += 1024) s += g_partial[i];
    red[tid] = s;
    __syncthreads();
    for (int o = 512; o > 0; o >>= 1) {
        if (tid < o) red[tid] += red[tid + o];
        __syncthreads();
    }
    if (tid == 0) {
        double b = (double)beta[0];
        double cst = 256.0 * log(b / (2.0 * M_PI)) - log(360.0);
        double ll = ((double)Nrows * cst + red[0]) / (double)Nrows;
        out[0] = (float)(-ll);
    }
}

// ---------------------------------------------------------------------------
extern "C" void kernel_launch(void* const* d_in, const int* in_sizes, int n_in,
                              void* d_out, int out_size) {
    const float* t    = (const float*)d_in[0];
    const float* W    = (const float*)d_in[1];
    const float* beta = (const float*)d_in[2];
    float* out = (float*)d_out;

    int N = in_sizes[0] / DIM;                                  // 131072
    long long off = (long long)out_size - (long long)N * KLAT;  // scalar slot first
    if (off < 0) off = 0;

    static int smem_set = 0;
    if (!smem_set) {
        cudaFuncSetAttribute(gtm_mma_kernel,
                             cudaFuncAttributeMaxDynamicSharedMemorySize, SMEM_TOTAL);
        smem_set = 1;
    }

    phi_kernel<<<(KLAT * MRBF + 255) / 256, 256>>>();
    y_kernel<<<KP, 128>>>(W);
    noop_kernel<<<1, 32>>>();
    int ntiles = N / TM;        // 2048
    gtm_mma_kernel<<<ntiles, NTHREADS, SMEM_TOTAL>>>(t, beta, out, off);
    final_kernel<<<1, 1024>>>(beta, out, N, ntiles);
}